// round 2
// baseline (speedup 1.0000x reference)
#include <cuda_runtime.h>
#include <cuda_bf16.h>
#include <math.h>
#include <float.h>

// Problem constants
#define BB 4
#define SS 2048
#define DD 1024
#define HH 16
#define DK 64
#define ALPHA 0.7f
#define OMALPHA 0.3f

typedef unsigned long long u64t;

// ---- packed f32x2 helpers (Blackwell FFMA2 path) ----
__device__ __forceinline__ u64t f2pack(float lo, float hi) {
    u64t r; asm("mov.b64 %0, {%1, %2};" : "=l"(r) : "f"(lo), "f"(hi)); return r;
}
__device__ __forceinline__ float2 f2unpack(u64t v) {
    float2 r; asm("mov.b64 {%0, %1}, %2;" : "=f"(r.x), "=f"(r.y) : "l"(v)); return r;
}
__device__ __forceinline__ u64t f2fma(u64t a, u64t b, u64t c) {
    u64t d; asm("fma.rn.f32x2 %0, %1, %2, %3;" : "=l"(d) : "l"(a), "l"(b), "l"(c)); return d;
}
__device__ __forceinline__ u64t f2mul(u64t a, u64t b) {
    u64t d; asm("mul.rn.f32x2 %0, %1, %2;" : "=l"(d) : "l"(a), "l"(b)); return d;
}
__device__ __forceinline__ u64t f2add(u64t a, u64t b) {
    u64t d; asm("add.rn.f32x2 %0, %1, %2;" : "=l"(d) : "l"(a), "l"(b)); return d;
}

// Scratch (device globals; allocation-free per harness rules)
__device__ float g_Q[BB * SS * DD];
__device__ float g_K[BB * SS * DD];
__device__ float g_V[BB * SS * DD];
__device__ float g_stats[BB * DD * 5];   // A0, A1c, A1s, A2c, A2s per (b,d)
__device__ int   g_anymaskzero;

// ---------------------------------------------------------------------------
// Kernel 0: zero scratch stats + mask flag
// ---------------------------------------------------------------------------
__global__ void zero_scratch_kernel() {
    int i = blockIdx.x * blockDim.x + threadIdx.x;
    if (i < BB * DD * 5) g_stats[i] = 0.0f;
    if (i == 0) g_anymaskzero = 0;
}

// ---------------------------------------------------------------------------
// Kernel 1: Fourier stats. low-pass = projection onto freq bins 0,1,2.
// ---------------------------------------------------------------------------
__global__ void fourier_stats_kernel(const float* __restrict__ x) {
    const int b = blockIdx.y;
    const int sc = blockIdx.x;
    const int tid = threadIdx.x;
    const float w0 = 6.283185307179586476925286766559f / (float)SS;

    float acc[4][5];
#pragma unroll
    for (int i = 0; i < 4; i++)
#pragma unroll
        for (int k = 0; k < 5; k++) acc[i][k] = 0.0f;

    for (int si = 0; si < SS / 16; si++) {
        const int s = sc * (SS / 16) + si;
        float s1, c1;
        sincosf(w0 * (float)s, &s1, &c1);
        const float c2 = c1 * c1 - s1 * s1;
        const float s2 = 2.0f * s1 * c1;
        const float* xp = x + ((size_t)(b * SS + s)) * DD + tid;
#pragma unroll
        for (int i = 0; i < 4; i++) {
            const float v = xp[i * 256];
            acc[i][0] += v;
            acc[i][1] += v * c1;
            acc[i][2] += v * s1;
            acc[i][3] += v * c2;
            acc[i][4] += v * s2;
        }
    }
#pragma unroll
    for (int i = 0; i < 4; i++) {
        const int d = i * 256 + tid;
        float* st = &g_stats[(b * DD + d) * 5];
        atomicAdd(&st[0], acc[i][0]);
        atomicAdd(&st[1], acc[i][1]);
        atomicAdd(&st[2], acc[i][2]);
        atomicAdd(&st[3], acc[i][3]);
        atomicAdd(&st[4], acc[i][4]);
    }
}

// ---------------------------------------------------------------------------
// Kernel 2: mask scan — set flag if any zero exists
// ---------------------------------------------------------------------------
__global__ void mask_scan_kernel(const int* __restrict__ mask, int n) {
    int i = blockIdx.x * blockDim.x + threadIdx.x;
    const int stride = gridDim.x * blockDim.x;
    bool z = false;
    for (; i < n; i += stride)
        if (mask[i] == 0) z = true;
    if (z) atomicExch(&g_anymaskzero, 1);
}

// ---------------------------------------------------------------------------
// Kernel 3: DSP branch + LayerNorm, writes ALPHA*dsp into out.
// ---------------------------------------------------------------------------
__global__ void dsp_ln_kernel(const float* __restrict__ x,
                              const float* __restrict__ sqrt_beta,
                              const float* __restrict__ gamma,
                              const float* __restrict__ lnb,
                              float* __restrict__ out) {
    const int bt = blockIdx.x;
    const int b = bt >> 11;
    const int t = bt & (SS - 1);
    const int tid = threadIdx.x;
    const float w0 = 6.283185307179586476925286766559f / (float)SS;

    float s1, c1;
    sincosf(w0 * (float)t, &s1, &c1);
    const float c2 = c1 * c1 - s1 * s1;
    const float s2 = 2.0f * s1 * c1;

    float y[4];
    float sum = 0.0f, sq = 0.0f;
#pragma unroll
    for (int i = 0; i < 4; i++) {
        const int d = i * 256 + tid;
        const float* st = &g_stats[(b * DD + d) * 5];
        const float lp = (st[0] + 2.0f * (st[1] * c1 + st[2] * s1)
                                + 2.0f * (st[3] * c2 + st[4] * s2)) * (1.0f / (float)SS);
        const float v = x[((size_t)(b * SS + t)) * DD + d];
        const float be = sqrt_beta[d];
        const float b2 = be * be;
        const float yy = (1.0f + b2) * v + (1.0f - b2) * lp;
        y[i] = yy;
        sum += yy;
        sq += yy * yy;
    }

    __shared__ float red[18];
#pragma unroll
    for (int o = 16; o; o >>= 1) {
        sum += __shfl_down_sync(0xffffffffu, sum, o);
        sq  += __shfl_down_sync(0xffffffffu, sq, o);
    }
    const int w = tid >> 5, ln = tid & 31;
    if (ln == 0) { red[w] = sum; red[w + 8] = sq; }
    __syncthreads();
    if (tid == 0) {
        float s = 0.0f, ssq = 0.0f;
        for (int i = 0; i < 8; i++) { s += red[i]; ssq += red[i + 8]; }
        red[16] = s; red[17] = ssq;
    }
    __syncthreads();
    sum = red[16]; sq = red[17];

    const float mu = sum * (1.0f / (float)DD);
    const float var = sq * (1.0f / (float)DD) - mu * mu;
    const float rs = rsqrtf(var + 1e-12f);
#pragma unroll
    for (int i = 0; i < 4; i++) {
        const int d = i * 256 + tid;
        out[((size_t)(b * SS + t)) * DD + d] =
            ALPHA * ((y[i] - mu) * rs * gamma[d] + lnb[d]);
    }
}

// ---------------------------------------------------------------------------
// Kernel 4: QKV GEMM with packed f32x2 FMA.
// C[m,n] = sum_k X[m,k]*W[n,k] + bias[n]. 128x128x8 tile, 256 threads.
// ---------------------------------------------------------------------------
__global__ __launch_bounds__(256) void gemm_qkv_kernel(
    const float* __restrict__ X,
    const float* __restrict__ qw, const float* __restrict__ qb,
    const float* __restrict__ kw, const float* __restrict__ kb,
    const float* __restrict__ vw, const float* __restrict__ vb) {
    const float* W; const float* bias; float* out;
    if (blockIdx.z == 0)      { W = qw; bias = qb; out = g_Q; }
    else if (blockIdx.z == 1) { W = kw; bias = kb; out = g_K; }
    else                      { W = vw; bias = vb; out = g_V; }

    __shared__ float As[8][128];
    __shared__ float Bs[8][128];

    const int tid = threadIdx.x;
    const int m0 = blockIdx.y * 128;
    const int n0 = blockIdx.x * 128;
    const int tx = tid & 15, ty = tid >> 4;

    u64t accp[8][4];
#pragma unroll
    for (int i = 0; i < 8; i++)
#pragma unroll
        for (int j = 0; j < 4; j++) accp[i][j] = 0ull;

    const int arow = tid >> 1;
    const int acol = (tid & 1) * 4;
    const float* Aptr = X + ((size_t)(m0 + arow)) * DD + acol;
    const float* Bptr = W + ((size_t)(n0 + arow)) * DD + acol;

    for (int k0 = 0; k0 < DD; k0 += 8) {
        const float4 av = *(const float4*)(Aptr + k0);
        const float4 bv = *(const float4*)(Bptr + k0);
        __syncthreads();
        As[acol + 0][arow] = av.x; As[acol + 1][arow] = av.y;
        As[acol + 2][arow] = av.z; As[acol + 3][arow] = av.w;
        Bs[acol + 0][arow] = bv.x; Bs[acol + 1][arow] = bv.y;
        Bs[acol + 2][arow] = bv.z; Bs[acol + 3][arow] = bv.w;
        __syncthreads();
#pragma unroll
        for (int k = 0; k < 8; k++) {
            float a[8];
            *(float4*)&a[0] = *(const float4*)&As[k][ty * 8];
            *(float4*)&a[4] = *(const float4*)&As[k][ty * 8 + 4];
            const ulonglong2 bq0 = *(const ulonglong2*)&Bs[k][tx * 8];
            const ulonglong2 bq1 = *(const ulonglong2*)&Bs[k][tx * 8 + 4];
            u64t b2[4];
            b2[0] = bq0.x; b2[1] = bq0.y; b2[2] = bq1.x; b2[3] = bq1.y;
#pragma unroll
            for (int i = 0; i < 8; i++) {
                const u64t a2 = f2pack(a[i], a[i]);
#pragma unroll
                for (int j = 0; j < 4; j++)
                    accp[i][j] = f2fma(a2, b2[j], accp[i][j]);
            }
        }
    }

    // bias pairs (bias[n], bias[n+1]) line up with acc pairs
    const ulonglong2 bb0 = *(const ulonglong2*)(bias + n0 + tx * 8);
    const ulonglong2 bb1 = *(const ulonglong2*)(bias + n0 + tx * 8 + 4);
    u64t biasp[4] = { bb0.x, bb0.y, bb1.x, bb1.y };

#pragma unroll
    for (int i = 0; i < 8; i++) {
        float* op = out + ((size_t)(m0 + ty * 8 + i)) * DD + n0 + tx * 8;
        ulonglong2 r0, r1;
        r0.x = f2add(accp[i][0], biasp[0]);
        r0.y = f2add(accp[i][1], biasp[1]);
        r1.x = f2add(accp[i][2], biasp[2]);
        r1.y = f2add(accp[i][3], biasp[3]);
        *(ulonglong2*)op = r0;
        *(ulonglong2*)(op + 4) = r1;
    }
}

// ---------------------------------------------------------------------------
// Kernel 5: flash attention (fp32, packed f32x2), adds (1-ALPHA)*gsp into out.
// grid (S/128, B*H). 128 threads, 1 query row per thread.
// ---------------------------------------------------------------------------
__global__ __launch_bounds__(128) void attn_kernel(const int* __restrict__ mask,
                                                   float* __restrict__ out) {
    const int qt = blockIdx.x;
    const int bh = blockIdx.y;
    const int b = bh >> 4, h = bh & 15;
    const int tid = threadIdx.x;
    const int qrow = qt * 128 + tid;

    __shared__ float sK[64 * 64];
    __shared__ float sV[64 * 64];

    // q as 32 packed pairs
    u64t q2[32];
    const ulonglong2* qp2 = (const ulonglong2*)(g_Q + ((size_t)(b * SS + qrow)) * DD + h * DK);
#pragma unroll
    for (int t = 0; t < 16; t++) {
        const ulonglong2 v = qp2[t];
        q2[2 * t] = v.x; q2[2 * t + 1] = v.y;
    }

    u64t O2[32];
#pragma unroll
    for (int k = 0; k < 32; k++) O2[k] = 0ull;
    float m = -FLT_MAX;
    float l = 0.0f;

    const int anyzero = g_anymaskzero;
    const int* mrow = mask + (size_t)qrow * SS;

    for (int kt = 0; kt < SS / 64; kt++) {
        const int j0 = kt * 64;
#pragma unroll
        for (int i = 0; i < 8; i++) {
            const int idx4 = tid + 128 * i;       // 0..1023 float4 slots
            const int r = idx4 >> 4;
            const int kq = (idx4 & 15) * 4;
            *(float4*)&sK[r * 64 + kq] =
                *(const float4*)(g_K + ((size_t)(b * SS + j0 + r)) * DD + h * DK + kq);
            *(float4*)&sV[r * 64 + kq] =
                *(const float4*)(g_V + ((size_t)(b * SS + j0 + r)) * DD + h * DK + kq);
        }
        __syncthreads();

        for (int j = 0; j < 64; j++) {
            bool ok = true;
            if (anyzero) ok = (mrow[j0 + j] != 0);
            const ulonglong2* kj = (const ulonglong2*)&sK[j * 64];
            u64t s0 = 0ull, s1 = 0ull, s2 = 0ull, s3 = 0ull;
#pragma unroll
            for (int t = 0; t < 8; t++) {
                const ulonglong2 ka = kj[2 * t];
                const ulonglong2 kb = kj[2 * t + 1];
                s0 = f2fma(q2[4 * t + 0], ka.x, s0);
                s1 = f2fma(q2[4 * t + 1], ka.y, s1);
                s2 = f2fma(q2[4 * t + 2], kb.x, s2);
                s3 = f2fma(q2[4 * t + 3], kb.y, s3);
            }
            s0 = f2add(s0, s1);
            s2 = f2add(s2, s3);
            s0 = f2add(s0, s2);
            const float2 sf = f2unpack(s0);
            float s = sf.x + sf.y;
            if (ok) {
                s *= 0.125f;  // 1/sqrt(64)
                float p;
                if (s > m) {
                    const float corr = __expf(m - s);
                    l *= corr;
                    const u64t c2 = f2pack(corr, corr);
#pragma unroll
                    for (int k = 0; k < 32; k++) O2[k] = f2mul(O2[k], c2);
                    m = s;
                    p = 1.0f;
                } else {
                    p = __expf(s - m);
                }
                l += p;
                const u64t p2 = f2pack(p, p);
                const ulonglong2* vj = (const ulonglong2*)&sV[j * 64];
#pragma unroll
                for (int t = 0; t < 16; t++) {
                    const ulonglong2 vv = vj[t];
                    O2[2 * t]     = f2fma(p2, vv.x, O2[2 * t]);
                    O2[2 * t + 1] = f2fma(p2, vv.y, O2[2 * t + 1]);
                }
            }
        }
        __syncthreads();
    }

    const float invl = (l > 0.0f) ? (1.0f / l) : 0.0f;
    const float wscale = OMALPHA * invl;
    const u64t w2 = f2pack(wscale, wscale);
    ulonglong2* op2 = (ulonglong2*)(out + ((size_t)(b * SS + qrow)) * DD + h * DK);
#pragma unroll
    for (int t = 0; t < 16; t++) {
        ulonglong2 cur = op2[t];
        cur.x = f2fma(w2, O2[2 * t],     cur.x);
        cur.y = f2fma(w2, O2[2 * t + 1], cur.y);
        op2[t] = cur;
    }
}

// ---------------------------------------------------------------------------
extern "C" void kernel_launch(void* const* d_in, const int* in_sizes, int n_in,
                              void* d_out, int out_size) {
    const float* x       = (const float*)d_in[0];
    const int*   mask    = (const int*)d_in[1];
    const float* sb      = (const float*)d_in[2];
    const float* gamma   = (const float*)d_in[3];
    const float* lnb     = (const float*)d_in[4];
    const float* qw      = (const float*)d_in[5];
    const float* qb      = (const float*)d_in[6];
    const float* kw      = (const float*)d_in[7];
    const float* kb      = (const float*)d_in[8];
    const float* vw      = (const float*)d_in[9];
    const float* vb      = (const float*)d_in[10];
    float* out = (float*)d_out;
    const int maskN = in_sizes[1];

    zero_scratch_kernel<<<(BB * DD * 5 + 255) / 256, 256>>>();
    fourier_stats_kernel<<<dim3(16, BB), 256>>>(x);
    mask_scan_kernel<<<512, 256>>>(mask, maskN);
    dsp_ln_kernel<<<BB * SS, 256>>>(x, sb, gamma, lnb, out);
    gemm_qkv_kernel<<<dim3(DD / 128, BB * SS / 128, 3), 256>>>(x, qw, qb, kw, kb, vw, vb);
    attn_kernel<<<dim3(SS / 128, BB * HH), 128>>>(mask, out);
}

// round 3
// speedup vs baseline: 1.2729x; 1.2729x over previous
#include <cuda_runtime.h>
#include <cuda_bf16.h>
#include <math.h>
#include <float.h>

// Problem constants
#define BB 4
#define SS 2048
#define DD 1024
#define HH 16
#define DK 64
#define ALPHA 0.7f
#define OMALPHA 0.3f

// GEMM tile
#define BM 128
#define BN 128
#define BKK 32
#define SROW 40   // padded smem row in bf16 (80B) -> conflict-free ldmatrix

// Scratch (device globals; allocation-free per harness rules)
__device__ float g_Q[BB * SS * DD];
__device__ float g_K[BB * SS * DD];
__device__ float g_V[BB * SS * DD];
__device__ float g_stats[BB * DD * 5];
__device__ int   g_anymaskzero;

__device__ __nv_bfloat16 g_Xhi[BB * SS * DD];
__device__ __nv_bfloat16 g_Xlo[BB * SS * DD];
__device__ __nv_bfloat16 g_Whi[3 * DD * DD];
__device__ __nv_bfloat16 g_Wlo[3 * DD * DD];

// ---- mma helpers ----
__device__ __forceinline__ unsigned sptr(const void* p) {
    return (unsigned)__cvta_generic_to_shared(p);
}
__device__ __forceinline__ void ldsm4(unsigned* r, unsigned addr) {
    asm volatile("ldmatrix.sync.aligned.m8n8.x4.shared.b16 {%0,%1,%2,%3}, [%4];\n"
                 : "=r"(r[0]), "=r"(r[1]), "=r"(r[2]), "=r"(r[3]) : "r"(addr));
}
__device__ __forceinline__ void mma_bf16(float* c, const unsigned* a, const unsigned* b) {
    asm volatile("mma.sync.aligned.m16n8k16.row.col.f32.bf16.bf16.f32 "
                 "{%0,%1,%2,%3}, {%4,%5,%6,%7}, {%8,%9}, {%0,%1,%2,%3};\n"
                 : "+f"(c[0]), "+f"(c[1]), "+f"(c[2]), "+f"(c[3])
                 : "r"(a[0]), "r"(a[1]), "r"(a[2]), "r"(a[3]), "r"(b[0]), "r"(b[1]));
}

// ---------------------------------------------------------------------------
// Kernel 0: zero scratch stats + mask flag
// ---------------------------------------------------------------------------
__global__ void zero_scratch_kernel() {
    int i = blockIdx.x * blockDim.x + threadIdx.x;
    if (i < BB * DD * 5) g_stats[i] = 0.0f;
    if (i == 0) g_anymaskzero = 0;
}

// ---------------------------------------------------------------------------
// Split fp32 -> bf16 hi/lo
// ---------------------------------------------------------------------------
__global__ void split_kernel(const float* __restrict__ src,
                             __nv_bfloat16* __restrict__ hi,
                             __nv_bfloat16* __restrict__ lo, int n4) {
    int i = blockIdx.x * blockDim.x + threadIdx.x;
    if (i >= n4) return;
    float4 v = ((const float4*)src)[i];
    __nv_bfloat16 h0 = __float2bfloat16(v.x);
    __nv_bfloat16 h1 = __float2bfloat16(v.y);
    __nv_bfloat16 h2 = __float2bfloat16(v.z);
    __nv_bfloat16 h3 = __float2bfloat16(v.w);
    __nv_bfloat162* hp = (__nv_bfloat162*)hi;
    __nv_bfloat162* lp = (__nv_bfloat162*)lo;
    hp[2 * i]     = __nv_bfloat162(h0, h1);
    hp[2 * i + 1] = __nv_bfloat162(h2, h3);
    lp[2 * i]     = __nv_bfloat162(__float2bfloat16(v.x - __bfloat162float(h0)),
                                   __float2bfloat16(v.y - __bfloat162float(h1)));
    lp[2 * i + 1] = __nv_bfloat162(__float2bfloat16(v.z - __bfloat162float(h2)),
                                   __float2bfloat16(v.w - __bfloat162float(h3)));
}

// ---------------------------------------------------------------------------
// Kernel 1: Fourier stats
// ---------------------------------------------------------------------------
__global__ void fourier_stats_kernel(const float* __restrict__ x) {
    const int b = blockIdx.y;
    const int sc = blockIdx.x;
    const int tid = threadIdx.x;
    const float w0 = 6.283185307179586476925286766559f / (float)SS;

    float acc[4][5];
#pragma unroll
    for (int i = 0; i < 4; i++)
#pragma unroll
        for (int k = 0; k < 5; k++) acc[i][k] = 0.0f;

    for (int si = 0; si < SS / 16; si++) {
        const int s = sc * (SS / 16) + si;
        float s1, c1;
        sincosf(w0 * (float)s, &s1, &c1);
        const float c2 = c1 * c1 - s1 * s1;
        const float s2 = 2.0f * s1 * c1;
        const float* xp = x + ((size_t)(b * SS + s)) * DD + tid;
#pragma unroll
        for (int i = 0; i < 4; i++) {
            const float v = xp[i * 256];
            acc[i][0] += v;
            acc[i][1] += v * c1;
            acc[i][2] += v * s1;
            acc[i][3] += v * c2;
            acc[i][4] += v * s2;
        }
    }
#pragma unroll
    for (int i = 0; i < 4; i++) {
        const int d = i * 256 + tid;
        float* st = &g_stats[(b * DD + d) * 5];
        atomicAdd(&st[0], acc[i][0]);
        atomicAdd(&st[1], acc[i][1]);
        atomicAdd(&st[2], acc[i][2]);
        atomicAdd(&st[3], acc[i][3]);
        atomicAdd(&st[4], acc[i][4]);
    }
}

// ---------------------------------------------------------------------------
// Kernel 2: mask scan
// ---------------------------------------------------------------------------
__global__ void mask_scan_kernel(const int* __restrict__ mask, int n) {
    int i = blockIdx.x * blockDim.x + threadIdx.x;
    const int stride = gridDim.x * blockDim.x;
    bool z = false;
    for (; i < n; i += stride)
        if (mask[i] == 0) z = true;
    if (z) atomicExch(&g_anymaskzero, 1);
}

// ---------------------------------------------------------------------------
// Kernel 3: DSP branch + LayerNorm -> ALPHA*dsp into out
// ---------------------------------------------------------------------------
__global__ void dsp_ln_kernel(const float* __restrict__ x,
                              const float* __restrict__ sqrt_beta,
                              const float* __restrict__ gamma,
                              const float* __restrict__ lnb,
                              float* __restrict__ out) {
    const int bt = blockIdx.x;
    const int b = bt >> 11;
    const int t = bt & (SS - 1);
    const int tid = threadIdx.x;
    const float w0 = 6.283185307179586476925286766559f / (float)SS;

    float s1, c1;
    sincosf(w0 * (float)t, &s1, &c1);
    const float c2 = c1 * c1 - s1 * s1;
    const float s2 = 2.0f * s1 * c1;

    float y[4];
    float sum = 0.0f, sq = 0.0f;
#pragma unroll
    for (int i = 0; i < 4; i++) {
        const int d = i * 256 + tid;
        const float* st = &g_stats[(b * DD + d) * 5];
        const float lp = (st[0] + 2.0f * (st[1] * c1 + st[2] * s1)
                                + 2.0f * (st[3] * c2 + st[4] * s2)) * (1.0f / (float)SS);
        const float v = x[((size_t)(b * SS + t)) * DD + d];
        const float be = sqrt_beta[d];
        const float b2 = be * be;
        const float yy = (1.0f + b2) * v + (1.0f - b2) * lp;
        y[i] = yy;
        sum += yy;
        sq += yy * yy;
    }

    __shared__ float red[18];
#pragma unroll
    for (int o = 16; o; o >>= 1) {
        sum += __shfl_down_sync(0xffffffffu, sum, o);
        sq  += __shfl_down_sync(0xffffffffu, sq, o);
    }
    const int w = tid >> 5, ln = tid & 31;
    if (ln == 0) { red[w] = sum; red[w + 8] = sq; }
    __syncthreads();
    if (tid == 0) {
        float s = 0.0f, ssq = 0.0f;
        for (int i = 0; i < 8; i++) { s += red[i]; ssq += red[i + 8]; }
        red[16] = s; red[17] = ssq;
    }
    __syncthreads();
    sum = red[16]; sq = red[17];

    const float mu = sum * (1.0f / (float)DD);
    const float var = sq * (1.0f / (float)DD) - mu * mu;
    const float rs = rsqrtf(var + 1e-12f);
#pragma unroll
    for (int i = 0; i < 4; i++) {
        const int d = i * 256 + tid;
        out[((size_t)(b * SS + t)) * DD + d] =
            ALPHA * ((y[i] - mu) * rs * gamma[d] + lnb[d]);
    }
}

// ---------------------------------------------------------------------------
// Kernel 4: QKV GEMM via tensor cores, split-bf16 (hi*hi + lo*hi + hi*lo).
// 128x128x32 tile, 256 threads = 8 warps (2 m x 4 n). Warp tile 64x32.
// ---------------------------------------------------------------------------
__global__ __launch_bounds__(256) void gemm_qkv_mma(
    const float* __restrict__ qb, const float* __restrict__ kb,
    const float* __restrict__ vb) {
    const int z = blockIdx.z;
    const __nv_bfloat16* Whi = g_Whi + (size_t)z * DD * DD;
    const __nv_bfloat16* Wlo = g_Wlo + (size_t)z * DD * DD;
    const float* bias; float* out;
    if (z == 0)      { bias = qb; out = g_Q; }
    else if (z == 1) { bias = kb; out = g_K; }
    else             { bias = vb; out = g_V; }

    __shared__ __nv_bfloat16 sAhi[BM][SROW];
    __shared__ __nv_bfloat16 sAlo[BM][SROW];
    __shared__ __nv_bfloat16 sBhi[BN][SROW];
    __shared__ __nv_bfloat16 sBlo[BN][SROW];

    const int tid = threadIdx.x;
    const int lane = tid & 31, warp = tid >> 5;
    const int wm = warp & 1, wn = warp >> 1;
    const int m0 = blockIdx.y * BM, n0 = blockIdx.x * BN;

    float acc[4][4][4];
#pragma unroll
    for (int a = 0; a < 4; a++)
#pragma unroll
        for (int b = 0; b < 4; b++)
#pragma unroll
            for (int c = 0; c < 4; c++) acc[a][b][c] = 0.0f;

    // gmem load mapping: row = tid>>1 (0..127), colbase = (tid&1)*16
    const int grow = tid >> 1;
    const int gcol = (tid & 1) * 16;
    const __nv_bfloat16* pAhi = g_Xhi + (size_t)(m0 + grow) * DD + gcol;
    const __nv_bfloat16* pAlo = g_Xlo + (size_t)(m0 + grow) * DD + gcol;
    const __nv_bfloat16* pBhi = Whi + (size_t)(n0 + grow) * DD + gcol;
    const __nv_bfloat16* pBlo = Wlo + (size_t)(n0 + grow) * DD + gcol;

    // ldmatrix base addresses
    const unsigned aHiBase = sptr(&sAhi[wm * 64 + (lane & 15)][(lane >> 4) * 8]);
    const unsigned aLoBase = sptr(&sAlo[wm * 64 + (lane & 15)][(lane >> 4) * 8]);
    const int j = lane >> 3;
    const unsigned bHiBase = sptr(&sBhi[wn * 32 + (j >> 1) * 8 + (lane & 7)][(j & 1) * 8]);
    const unsigned bLoBase = sptr(&sBlo[wn * 32 + (j >> 1) * 8 + (lane & 7)][(j & 1) * 8]);
    const unsigned ROWB = SROW * 2;   // 80 bytes per smem row

    uint4 va0, va1, vb0, vb1, vc0, vc1, vd0, vd1;
    // prologue loads (kb = 0)
    va0 = *(const uint4*)(pAhi);     va1 = *(const uint4*)(pAhi + 8);
    vb0 = *(const uint4*)(pAlo);     vb1 = *(const uint4*)(pAlo + 8);
    vc0 = *(const uint4*)(pBhi);     vc1 = *(const uint4*)(pBhi + 8);
    vd0 = *(const uint4*)(pBlo);     vd1 = *(const uint4*)(pBlo + 8);

    for (int kbase = 0; kbase < DD; kbase += BKK) {
        __syncthreads();
        *(uint4*)&sAhi[grow][gcol] = va0; *(uint4*)&sAhi[grow][gcol + 8] = va1;
        *(uint4*)&sAlo[grow][gcol] = vb0; *(uint4*)&sAlo[grow][gcol + 8] = vb1;
        *(uint4*)&sBhi[grow][gcol] = vc0; *(uint4*)&sBhi[grow][gcol + 8] = vc1;
        *(uint4*)&sBlo[grow][gcol] = vd0; *(uint4*)&sBlo[grow][gcol + 8] = vd1;
        __syncthreads();

        const int kn = kbase + BKK;
        if (kn < DD) {   // prefetch next tile while computing
            va0 = *(const uint4*)(pAhi + kn); va1 = *(const uint4*)(pAhi + kn + 8);
            vb0 = *(const uint4*)(pAlo + kn); vb1 = *(const uint4*)(pAlo + kn + 8);
            vc0 = *(const uint4*)(pBhi + kn); vc1 = *(const uint4*)(pBhi + kn + 8);
            vd0 = *(const uint4*)(pBlo + kn); vd1 = *(const uint4*)(pBlo + kn + 8);
        }

#pragma unroll
        for (int ks = 0; ks < 2; ks++) {
            unsigned ah[4][4], al[4][4], bh[2][4], bl[2][4];
#pragma unroll
            for (int mt = 0; mt < 4; mt++) {
                ldsm4(ah[mt], aHiBase + mt * 16 * ROWB + ks * 32);
                ldsm4(al[mt], aLoBase + mt * 16 * ROWB + ks * 32);
            }
#pragma unroll
            for (int np = 0; np < 2; np++) {
                ldsm4(bh[np], bHiBase + np * 16 * ROWB + ks * 32);
                ldsm4(bl[np], bLoBase + np * 16 * ROWB + ks * 32);
            }
#pragma unroll
            for (int mt = 0; mt < 4; mt++)
#pragma unroll
                for (int nt = 0; nt < 4; nt++) {
                    const unsigned* bhp = &bh[nt >> 1][(nt & 1) * 2];
                    const unsigned* blp = &bl[nt >> 1][(nt & 1) * 2];
                    mma_bf16(acc[mt][nt], ah[mt], bhp);
                    mma_bf16(acc[mt][nt], al[mt], bhp);
                    mma_bf16(acc[mt][nt], ah[mt], blp);
                }
        }
    }

    // epilogue: bias + fp32 store
#pragma unroll
    for (int nt = 0; nt < 4; nt++) {
        const int col = n0 + wn * 32 + nt * 8 + (lane & 3) * 2;
        const float bx = bias[col], by = bias[col + 1];
#pragma unroll
        for (int mt = 0; mt < 4; mt++) {
            const int r = m0 + wm * 64 + mt * 16 + (lane >> 2);
            float2 lo2, hi2;
            lo2.x = acc[mt][nt][0] + bx; lo2.y = acc[mt][nt][1] + by;
            hi2.x = acc[mt][nt][2] + bx; hi2.y = acc[mt][nt][3] + by;
            *(float2*)&out[(size_t)r * DD + col] = lo2;
            *(float2*)&out[(size_t)(r + 8) * DD + col] = hi2;
        }
    }
}

// ---------------------------------------------------------------------------
// Kernel 5: flash attention (fp32 scalar, proven R1 version)
// ---------------------------------------------------------------------------
__global__ __launch_bounds__(128) void attn_kernel(const int* __restrict__ mask,
                                                   float* __restrict__ out) {
    const int qt = blockIdx.x;
    const int bh = blockIdx.y;
    const int b = bh >> 4, h = bh & 15;
    const int tid = threadIdx.x;
    const int qrow = qt * 128 + tid;

    __shared__ float sK[64 * 64];
    __shared__ float sV[64 * 64];

    float q[64];
    const float* qp = g_Q + ((size_t)(b * SS + qrow)) * DD + h * DK;
#pragma unroll
    for (int k4 = 0; k4 < 16; k4++)
        *(float4*)&q[k4 * 4] = *(const float4*)(qp + k4 * 4);

    float O[64];
#pragma unroll
    for (int k = 0; k < 64; k++) O[k] = 0.0f;
    float m = -FLT_MAX;
    float l = 0.0f;

    const int anyzero = g_anymaskzero;
    const int* mrow = mask + (size_t)qrow * SS;

    for (int kt = 0; kt < SS / 64; kt++) {
        const int j0 = kt * 64;
#pragma unroll
        for (int i = 0; i < 8; i++) {
            const int idx4 = tid + 128 * i;
            const int r = idx4 >> 4;
            const int kq = (idx4 & 15) * 4;
            *(float4*)&sK[r * 64 + kq] =
                *(const float4*)(g_K + ((size_t)(b * SS + j0 + r)) * DD + h * DK + kq);
            *(float4*)&sV[r * 64 + kq] =
                *(const float4*)(g_V + ((size_t)(b * SS + j0 + r)) * DD + h * DK + kq);
        }
        __syncthreads();

        for (int jj = 0; jj < 64; jj++) {
            bool ok = true;
            if (anyzero) ok = (mrow[j0 + jj] != 0);
            float s = 0.0f;
            const float* kj = &sK[jj * 64];
#pragma unroll
            for (int k4 = 0; k4 < 16; k4++) {
                const float4 kv = *(const float4*)(kj + k4 * 4);
                s = fmaf(q[k4 * 4 + 0], kv.x, s);
                s = fmaf(q[k4 * 4 + 1], kv.y, s);
                s = fmaf(q[k4 * 4 + 2], kv.z, s);
                s = fmaf(q[k4 * 4 + 3], kv.w, s);
            }
            if (ok) {
                s *= 0.125f;
                float p;
                if (s > m) {
                    const float corr = __expf(m - s);
                    l *= corr;
#pragma unroll
                    for (int k = 0; k < 64; k++) O[k] *= corr;
                    m = s;
                    p = 1.0f;
                } else {
                    p = __expf(s - m);
                }
                l += p;
                const float* vj = &sV[jj * 64];
#pragma unroll
                for (int k4 = 0; k4 < 16; k4++) {
                    const float4 vv = *(const float4*)(vj + k4 * 4);
                    O[k4 * 4 + 0] = fmaf(p, vv.x, O[k4 * 4 + 0]);
                    O[k4 * 4 + 1] = fmaf(p, vv.y, O[k4 * 4 + 1]);
                    O[k4 * 4 + 2] = fmaf(p, vv.z, O[k4 * 4 + 2]);
                    O[k4 * 4 + 3] = fmaf(p, vv.w, O[k4 * 4 + 3]);
                }
            }
        }
        __syncthreads();
    }

    const float invl = (l > 0.0f) ? (1.0f / l) : 0.0f;
    float* op = out + ((size_t)(b * SS + qrow)) * DD + h * DK;
#pragma unroll
    for (int k = 0; k < 64; k++)
        op[k] = op[k] + OMALPHA * O[k] * invl;
}

// ---------------------------------------------------------------------------
extern "C" void kernel_launch(void* const* d_in, const int* in_sizes, int n_in,
                              void* d_out, int out_size) {
    const float* x       = (const float*)d_in[0];
    const int*   mask    = (const int*)d_in[1];
    const float* sb      = (const float*)d_in[2];
    const float* gamma   = (const float*)d_in[3];
    const float* lnb     = (const float*)d_in[4];
    const float* qw      = (const float*)d_in[5];
    const float* qb      = (const float*)d_in[6];
    const float* kw      = (const float*)d_in[7];
    const float* kb      = (const float*)d_in[8];
    const float* vw      = (const float*)d_in[9];
    const float* vb      = (const float*)d_in[10];
    float* out = (float*)d_out;
    const int maskN = in_sizes[1];

    // bf16 hi/lo splits
    __nv_bfloat16 *xhi = nullptr, *xlo = nullptr, *whi = nullptr, *wlo = nullptr;
    cudaGetSymbolAddress((void**)&xhi, g_Xhi);
    cudaGetSymbolAddress((void**)&xlo, g_Xlo);
    cudaGetSymbolAddress((void**)&whi, g_Whi);
    cudaGetSymbolAddress((void**)&wlo, g_Wlo);

    const int nX4 = BB * SS * DD / 4;
    const int nW4 = DD * DD / 4;
    split_kernel<<<(nX4 + 255) / 256, 256>>>(x, xhi, xlo, nX4);
    split_kernel<<<(nW4 + 255) / 256, 256>>>(qw, whi, wlo, nW4);
    split_kernel<<<(nW4 + 255) / 256, 256>>>(kw, whi + (size_t)DD * DD, wlo + (size_t)DD * DD, nW4);
    split_kernel<<<(nW4 + 255) / 256, 256>>>(vw, whi + (size_t)2 * DD * DD, wlo + (size_t)2 * DD * DD, nW4);

    zero_scratch_kernel<<<(BB * DD * 5 + 255) / 256, 256>>>();
    fourier_stats_kernel<<<dim3(16, BB), 256>>>(x);
    mask_scan_kernel<<<512, 256>>>(mask, maskN);
    dsp_ln_kernel<<<BB * SS, 256>>>(x, sb, gamma, lnb, out);
    gemm_qkv_mma<<<dim3(BN == 128 ? DD / BN : 0, BB * SS / BM, 3), 256>>>(qb, kb, vb);
    attn_kernel<<<dim3(SS / 128, BB * HH), 128>>>(mask, out);
}

// round 5
// speedup vs baseline: 3.6789x; 2.8901x over previous
#include <cuda_runtime.h>
#include <cuda_bf16.h>
#include <math.h>
#include <float.h>

// Problem constants
#define BB 4
#define SS 2048
#define DD 1024
#define HH 16
#define DK 64
#define ALPHA 0.7f
#define OMALPHA 0.3f

// GEMM tile
#define BM 128
#define BN 128
#define BKK 32
#define SROW 40   // padded smem row in bf16 (80B) -> conflict-free ldmatrix

// Attention smem row stride (64 data + 8 pad)
#define VROW 72

// Scratch (device globals; allocation-free per harness rules)
__device__ float g_stats[BB * DD * 5];
__device__ int   g_anymaskzero;

__device__ __nv_bfloat16 g_Xhi[BB * SS * DD];
__device__ __nv_bfloat16 g_Xlo[BB * SS * DD];
__device__ __nv_bfloat16 g_Whi[3 * DD * DD];
__device__ __nv_bfloat16 g_Wlo[3 * DD * DD];

__device__ __nv_bfloat16 g_Qhi[BB * SS * DD];
__device__ __nv_bfloat16 g_Qlo[BB * SS * DD];
__device__ __nv_bfloat16 g_Khi[BB * SS * DD];
__device__ __nv_bfloat16 g_Klo[BB * SS * DD];
__device__ __nv_bfloat16 g_Vhi[BB * SS * DD];

// ---- mma helpers ----
__device__ __forceinline__ unsigned sptr(const void* p) {
    return (unsigned)__cvta_generic_to_shared(p);
}
__device__ __forceinline__ void ldsm4(unsigned* r, unsigned addr) {
    asm volatile("ldmatrix.sync.aligned.m8n8.x4.shared.b16 {%0,%1,%2,%3}, [%4];\n"
                 : "=r"(r[0]), "=r"(r[1]), "=r"(r[2]), "=r"(r[3]) : "r"(addr));
}
__device__ __forceinline__ void ldsm4t(unsigned* r, unsigned addr) {
    asm volatile("ldmatrix.sync.aligned.m8n8.x4.trans.shared.b16 {%0,%1,%2,%3}, [%4];\n"
                 : "=r"(r[0]), "=r"(r[1]), "=r"(r[2]), "=r"(r[3]) : "r"(addr));
}
__device__ __forceinline__ void mma_bf16(float* c, const unsigned* a, const unsigned* b) {
    asm volatile("mma.sync.aligned.m16n8k16.row.col.f32.bf16.bf16.f32 "
                 "{%0,%1,%2,%3}, {%4,%5,%6,%7}, {%8,%9}, {%0,%1,%2,%3};\n"
                 : "+f"(c[0]), "+f"(c[1]), "+f"(c[2]), "+f"(c[3])
                 : "r"(a[0]), "r"(a[1]), "r"(a[2]), "r"(a[3]), "r"(b[0]), "r"(b[1]));
}
__device__ __forceinline__ void mma_bf16s(float* c, const unsigned* a, unsigned b0, unsigned b1) {
    asm volatile("mma.sync.aligned.m16n8k16.row.col.f32.bf16.bf16.f32 "
                 "{%0,%1,%2,%3}, {%4,%5,%6,%7}, {%8,%9}, {%0,%1,%2,%3};\n"
                 : "+f"(c[0]), "+f"(c[1]), "+f"(c[2]), "+f"(c[3])
                 : "r"(a[0]), "r"(a[1]), "r"(a[2]), "r"(a[3]), "r"(b0), "r"(b1));
}
__device__ __forceinline__ unsigned packbf2(float lo, float hi) {
    __nv_bfloat162 v = __floats2bfloat162_rn(lo, hi);
    return *(unsigned*)&v;
}

// ---------------------------------------------------------------------------
// Kernel 0: zero scratch stats + mask flag
// ---------------------------------------------------------------------------
__global__ void zero_scratch_kernel() {
    int i = blockIdx.x * blockDim.x + threadIdx.x;
    if (i < BB * DD * 5) g_stats[i] = 0.0f;
    if (i == 0) g_anymaskzero = 0;
}

// ---------------------------------------------------------------------------
// Split fp32 -> bf16 hi/lo
// ---------------------------------------------------------------------------
__global__ void split_kernel(const float* __restrict__ src,
                             __nv_bfloat16* __restrict__ hi,
                             __nv_bfloat16* __restrict__ lo, int n4) {
    int i = blockIdx.x * blockDim.x + threadIdx.x;
    if (i >= n4) return;
    float4 v = ((const float4*)src)[i];
    __nv_bfloat16 h0 = __float2bfloat16(v.x);
    __nv_bfloat16 h1 = __float2bfloat16(v.y);
    __nv_bfloat16 h2 = __float2bfloat16(v.z);
    __nv_bfloat16 h3 = __float2bfloat16(v.w);
    __nv_bfloat162* hp = (__nv_bfloat162*)hi;
    __nv_bfloat162* lp = (__nv_bfloat162*)lo;
    hp[2 * i]     = __nv_bfloat162(h0, h1);
    hp[2 * i + 1] = __nv_bfloat162(h2, h3);
    lp[2 * i]     = __nv_bfloat162(__float2bfloat16(v.x - __bfloat162float(h0)),
                                   __float2bfloat16(v.y - __bfloat162float(h1)));
    lp[2 * i + 1] = __nv_bfloat162(__float2bfloat16(v.z - __bfloat162float(h2)),
                                   __float2bfloat16(v.w - __bfloat162float(h3)));
}

// ---------------------------------------------------------------------------
// Kernel 1: Fourier stats
// ---------------------------------------------------------------------------
__global__ void fourier_stats_kernel(const float* __restrict__ x) {
    const int b = blockIdx.y;
    const int sc = blockIdx.x;
    const int tid = threadIdx.x;
    const float w0 = 6.283185307179586476925286766559f / (float)SS;

    float acc[4][5];
#pragma unroll
    for (int i = 0; i < 4; i++)
#pragma unroll
        for (int k = 0; k < 5; k++) acc[i][k] = 0.0f;

    for (int si = 0; si < SS / 16; si++) {
        const int s = sc * (SS / 16) + si;
        float s1, c1;
        sincosf(w0 * (float)s, &s1, &c1);
        const float c2 = c1 * c1 - s1 * s1;
        const float s2 = 2.0f * s1 * c1;
        const float* xp = x + ((size_t)(b * SS + s)) * DD + tid;
#pragma unroll
        for (int i = 0; i < 4; i++) {
            const float v = xp[i * 256];
            acc[i][0] += v;
            acc[i][1] += v * c1;
            acc[i][2] += v * s1;
            acc[i][3] += v * c2;
            acc[i][4] += v * s2;
        }
    }
#pragma unroll
    for (int i = 0; i < 4; i++) {
        const int d = i * 256 + tid;
        float* st = &g_stats[(b * DD + d) * 5];
        atomicAdd(&st[0], acc[i][0]);
        atomicAdd(&st[1], acc[i][1]);
        atomicAdd(&st[2], acc[i][2]);
        atomicAdd(&st[3], acc[i][3]);
        atomicAdd(&st[4], acc[i][4]);
    }
}

// ---------------------------------------------------------------------------
// Kernel 2: mask scan
// ---------------------------------------------------------------------------
__global__ void mask_scan_kernel(const int* __restrict__ mask, int n) {
    int i = blockIdx.x * blockDim.x + threadIdx.x;
    const int stride = gridDim.x * blockDim.x;
    bool z = false;
    for (; i < n; i += stride)
        if (mask[i] == 0) z = true;
    if (z) atomicExch(&g_anymaskzero, 1);
}

// ---------------------------------------------------------------------------
// Kernel 3: DSP branch + LayerNorm -> ALPHA*dsp into out
// ---------------------------------------------------------------------------
__global__ void dsp_ln_kernel(const float* __restrict__ x,
                              const float* __restrict__ sqrt_beta,
                              const float* __restrict__ gamma,
                              const float* __restrict__ lnb,
                              float* __restrict__ out) {
    const int bt = blockIdx.x;
    const int b = bt >> 11;
    const int t = bt & (SS - 1);
    const int tid = threadIdx.x;
    const float w0 = 6.283185307179586476925286766559f / (float)SS;

    float s1, c1;
    sincosf(w0 * (float)t, &s1, &c1);
    const float c2 = c1 * c1 - s1 * s1;
    const float s2 = 2.0f * s1 * c1;

    float y[4];
    float sum = 0.0f, sq = 0.0f;
#pragma unroll
    for (int i = 0; i < 4; i++) {
        const int d = i * 256 + tid;
        const float* st = &g_stats[(b * DD + d) * 5];
        const float lp = (st[0] + 2.0f * (st[1] * c1 + st[2] * s1)
                                + 2.0f * (st[3] * c2 + st[4] * s2)) * (1.0f / (float)SS);
        const float v = x[((size_t)(b * SS + t)) * DD + d];
        const float be = sqrt_beta[d];
        const float b2 = be * be;
        const float yy = (1.0f + b2) * v + (1.0f - b2) * lp;
        y[i] = yy;
        sum += yy;
        sq += yy * yy;
    }

    __shared__ float red[18];
#pragma unroll
    for (int o = 16; o; o >>= 1) {
        sum += __shfl_down_sync(0xffffffffu, sum, o);
        sq  += __shfl_down_sync(0xffffffffu, sq, o);
    }
    const int w = tid >> 5, ln = tid & 31;
    if (ln == 0) { red[w] = sum; red[w + 8] = sq; }
    __syncthreads();
    if (tid == 0) {
        float s = 0.0f, ssq = 0.0f;
        for (int i = 0; i < 8; i++) { s += red[i]; ssq += red[i + 8]; }
        red[16] = s; red[17] = ssq;
    }
    __syncthreads();
    sum = red[16]; sq = red[17];

    const float mu = sum * (1.0f / (float)DD);
    const float var = sq * (1.0f / (float)DD) - mu * mu;
    const float rs = rsqrtf(var + 1e-12f);
#pragma unroll
    for (int i = 0; i < 4; i++) {
        const int d = i * 256 + tid;
        out[((size_t)(b * SS + t)) * DD + d] =
            ALPHA * ((y[i] - mu) * rs * gamma[d] + lnb[d]);
    }
}

// ---------------------------------------------------------------------------
// Kernel 4: QKV GEMM via tensor cores, split-bf16 (hi*hi + lo*hi + hi*lo).
// Epilogue writes bf16 hi/lo for Q,K and bf16 hi for V (attention inputs).
// ---------------------------------------------------------------------------
__global__ __launch_bounds__(256) void gemm_qkv_mma(
    const float* __restrict__ qb, const float* __restrict__ kb,
    const float* __restrict__ vb) {
    const int z = blockIdx.z;
    const __nv_bfloat16* Whi = g_Whi + (size_t)z * DD * DD;
    const __nv_bfloat16* Wlo = g_Wlo + (size_t)z * DD * DD;
    const float* bias;
    __nv_bfloat16 *ohi, *olo;
    if (z == 0)      { bias = qb; ohi = g_Qhi; olo = g_Qlo; }
    else if (z == 1) { bias = kb; ohi = g_Khi; olo = g_Klo; }
    else             { bias = vb; ohi = g_Vhi; olo = nullptr; }

    __shared__ __nv_bfloat16 sAhi[BM][SROW];
    __shared__ __nv_bfloat16 sAlo[BM][SROW];
    __shared__ __nv_bfloat16 sBhi[BN][SROW];
    __shared__ __nv_bfloat16 sBlo[BN][SROW];

    const int tid = threadIdx.x;
    const int lane = tid & 31, warp = tid >> 5;
    const int wm = warp & 1, wn = warp >> 1;
    const int m0 = blockIdx.y * BM, n0 = blockIdx.x * BN;

    float acc[4][4][4];
#pragma unroll
    for (int a = 0; a < 4; a++)
#pragma unroll
        for (int b = 0; b < 4; b++)
#pragma unroll
            for (int c = 0; c < 4; c++) acc[a][b][c] = 0.0f;

    const int grow = tid >> 1;
    const int gcol = (tid & 1) * 16;
    const __nv_bfloat16* pAhi = g_Xhi + (size_t)(m0 + grow) * DD + gcol;
    const __nv_bfloat16* pAlo = g_Xlo + (size_t)(m0 + grow) * DD + gcol;
    const __nv_bfloat16* pBhi = Whi + (size_t)(n0 + grow) * DD + gcol;
    const __nv_bfloat16* pBlo = Wlo + (size_t)(n0 + grow) * DD + gcol;

    const unsigned aHiBase = sptr(&sAhi[wm * 64 + (lane & 15)][(lane >> 4) * 8]);
    const unsigned aLoBase = sptr(&sAlo[wm * 64 + (lane & 15)][(lane >> 4) * 8]);
    const int j = lane >> 3;
    const unsigned bHiBase = sptr(&sBhi[wn * 32 + (j >> 1) * 8 + (lane & 7)][(j & 1) * 8]);
    const unsigned bLoBase = sptr(&sBlo[wn * 32 + (j >> 1) * 8 + (lane & 7)][(j & 1) * 8]);
    const unsigned ROWB = SROW * 2;

    uint4 va0, va1, vb0, vb1, vc0, vc1, vd0, vd1;
    va0 = *(const uint4*)(pAhi);     va1 = *(const uint4*)(pAhi + 8);
    vb0 = *(const uint4*)(pAlo);     vb1 = *(const uint4*)(pAlo + 8);
    vc0 = *(const uint4*)(pBhi);     vc1 = *(const uint4*)(pBhi + 8);
    vd0 = *(const uint4*)(pBlo);     vd1 = *(const uint4*)(pBlo + 8);

    for (int kbase = 0; kbase < DD; kbase += BKK) {
        __syncthreads();
        *(uint4*)&sAhi[grow][gcol] = va0; *(uint4*)&sAhi[grow][gcol + 8] = va1;
        *(uint4*)&sAlo[grow][gcol] = vb0; *(uint4*)&sAlo[grow][gcol + 8] = vb1;
        *(uint4*)&sBhi[grow][gcol] = vc0; *(uint4*)&sBhi[grow][gcol + 8] = vc1;
        *(uint4*)&sBlo[grow][gcol] = vd0; *(uint4*)&sBlo[grow][gcol + 8] = vd1;
        __syncthreads();

        const int kn = kbase + BKK;
        if (kn < DD) {
            va0 = *(const uint4*)(pAhi + kn); va1 = *(const uint4*)(pAhi + kn + 8);
            vb0 = *(const uint4*)(pAlo + kn); vb1 = *(const uint4*)(pAlo + kn + 8);
            vc0 = *(const uint4*)(pBhi + kn); vc1 = *(const uint4*)(pBhi + kn + 8);
            vd0 = *(const uint4*)(pBlo + kn); vd1 = *(const uint4*)(pBlo + kn + 8);
        }

#pragma unroll
        for (int ks = 0; ks < 2; ks++) {
            unsigned ah[4][4], al[4][4], bh[2][4], bl[2][4];
#pragma unroll
            for (int mt = 0; mt < 4; mt++) {
                ldsm4(ah[mt], aHiBase + mt * 16 * ROWB + ks * 32);
                ldsm4(al[mt], aLoBase + mt * 16 * ROWB + ks * 32);
            }
#pragma unroll
            for (int np = 0; np < 2; np++) {
                ldsm4(bh[np], bHiBase + np * 16 * ROWB + ks * 32);
                ldsm4(bl[np], bLoBase + np * 16 * ROWB + ks * 32);
            }
#pragma unroll
            for (int mt = 0; mt < 4; mt++)
#pragma unroll
                for (int nt = 0; nt < 4; nt++) {
                    const unsigned* bhp = &bh[nt >> 1][(nt & 1) * 2];
                    const unsigned* blp = &bl[nt >> 1][(nt & 1) * 2];
                    mma_bf16(acc[mt][nt], ah[mt], bhp);
                    mma_bf16(acc[mt][nt], al[mt], bhp);
                    mma_bf16(acc[mt][nt], ah[mt], blp);
                }
        }
    }

    // epilogue: bias + hi/lo bf16 store
#pragma unroll
    for (int nt = 0; nt < 4; nt++) {
        const int col = n0 + wn * 32 + nt * 8 + (lane & 3) * 2;
        const float bx = bias[col], by = bias[col + 1];
#pragma unroll
        for (int mt = 0; mt < 4; mt++) {
            const int r = m0 + wm * 64 + mt * 16 + (lane >> 2);
            const float c0 = acc[mt][nt][0] + bx, c1 = acc[mt][nt][1] + by;
            const float c2 = acc[mt][nt][2] + bx, c3 = acc[mt][nt][3] + by;
            __nv_bfloat16 h0 = __float2bfloat16(c0), h1 = __float2bfloat16(c1);
            __nv_bfloat16 h2 = __float2bfloat16(c2), h3 = __float2bfloat16(c3);
            *(__nv_bfloat162*)&ohi[(size_t)r * DD + col] = __nv_bfloat162(h0, h1);
            *(__nv_bfloat162*)&ohi[(size_t)(r + 8) * DD + col] = __nv_bfloat162(h2, h3);
            if (z < 2) {
                *(__nv_bfloat162*)&olo[(size_t)r * DD + col] =
                    __nv_bfloat162(__float2bfloat16(c0 - __bfloat162float(h0)),
                                   __float2bfloat16(c1 - __bfloat162float(h1)));
                *(__nv_bfloat162*)&olo[(size_t)(r + 8) * DD + col] =
                    __nv_bfloat162(__float2bfloat16(c2 - __bfloat162float(h2)),
                                   __float2bfloat16(c3 - __bfloat162float(h3)));
            }
        }
    }
}

// ---------------------------------------------------------------------------
// Kernel 5: tensor-core flash attention.
// grid (SS/128, B*H), 256 threads (8 warps), each warp owns 16 q-rows.
// QK^T: 3-pass split bf16; PV: bf16 P (register reuse) x bf16 V (ldmatrix.trans)
// ---------------------------------------------------------------------------
__global__ __launch_bounds__(256, 1) void attn_mma_kernel(
    const int* __restrict__ mask, float* __restrict__ out) {
    const int qt = blockIdx.x;
    const int bh = blockIdx.y;
    const int b = bh >> 4, h = bh & 15;
    const int tid = threadIdx.x;
    const int lane = tid & 31, warp = tid >> 5;

    __shared__ __nv_bfloat16 sKh[64 * VROW];
    __shared__ __nv_bfloat16 sKl[64 * VROW];
    __shared__ __nv_bfloat16 sVh[64 * VROW];

    const int m0 = qt * 128 + warp * 16;
    const int r0 = m0 + (lane >> 2);
    const int r1 = r0 + 8;
    const int lc = (lane & 3) * 2;

    // Q fragments direct from gmem (fixed for whole kernel)
    unsigned qh[4][4], ql[4][4];
#pragma unroll
    for (int kk = 0; kk < 4; kk++) {
        const int dbase = h * 64 + kk * 16 + lc;
        qh[kk][0] = *(const unsigned*)&g_Qhi[(size_t)(b * SS + r0) * DD + dbase];
        qh[kk][1] = *(const unsigned*)&g_Qhi[(size_t)(b * SS + r1) * DD + dbase];
        qh[kk][2] = *(const unsigned*)&g_Qhi[(size_t)(b * SS + r0) * DD + dbase + 8];
        qh[kk][3] = *(const unsigned*)&g_Qhi[(size_t)(b * SS + r1) * DD + dbase + 8];
        ql[kk][0] = *(const unsigned*)&g_Qlo[(size_t)(b * SS + r0) * DD + dbase];
        ql[kk][1] = *(const unsigned*)&g_Qlo[(size_t)(b * SS + r1) * DD + dbase];
        ql[kk][2] = *(const unsigned*)&g_Qlo[(size_t)(b * SS + r0) * DD + dbase + 8];
        ql[kk][3] = *(const unsigned*)&g_Qlo[(size_t)(b * SS + r1) * DD + dbase + 8];
    }

    float o[8][4];
#pragma unroll
    for (int nt = 0; nt < 8; nt++)
#pragma unroll
        for (int c = 0; c < 4; c++) o[nt][c] = 0.0f;
    float mrow0 = -1e30f, mrow1 = -1e30f;
    float lrow0 = 0.0f, lrow1 = 0.0f;

    const int anyzero = g_anymaskzero;

    const int j = lane >> 3;
    const unsigned bRowCol = ((unsigned)((j >> 1) * 8 + (lane & 7))) * (VROW * 2) + (j & 1) * 16;
    const unsigned kHiBase = sptr(sKh) + bRowCol;
    const unsigned kLoBase = sptr(sKl) + bRowCol;
    const unsigned vBase   = sptr(sVh) + bRowCol;
    const unsigned ROWB = VROW * 2;

    for (int kt = 0; kt < SS / 64; kt++) {
        const int j0 = kt * 64;
        __syncthreads();
#pragma unroll
        for (int it = 0; it < 2; it++) {
            const int idx = tid + 256 * it;
            const int row = idx >> 3;
            const int c8 = (idx & 7) * 8;
            const size_t goff = (size_t)(b * SS + j0 + row) * DD + h * 64 + c8;
            *(uint4*)&sKh[row * VROW + c8] = *(const uint4*)&g_Khi[goff];
            *(uint4*)&sKl[row * VROW + c8] = *(const uint4*)&g_Klo[goff];
            *(uint4*)&sVh[row * VROW + c8] = *(const uint4*)&g_Vhi[goff];
        }
        __syncthreads();

        // ---- S = Q K^T (3-pass split bf16) ----
        float s[8][4];
#pragma unroll
        for (int nt = 0; nt < 8; nt++)
#pragma unroll
            for (int c = 0; c < 4; c++) s[nt][c] = 0.0f;

#pragma unroll
        for (int kk = 0; kk < 4; kk++) {
            unsigned kh[4][4], kl[4][4];
#pragma unroll
            for (int ng = 0; ng < 4; ng++) {
                ldsm4(kh[ng], kHiBase + ng * 16 * ROWB + kk * 32);
                ldsm4(kl[ng], kLoBase + ng * 16 * ROWB + kk * 32);
            }
#pragma unroll
            for (int ng = 0; ng < 4; ng++)
#pragma unroll
                for (int hf = 0; hf < 2; hf++) {
                    const int nt = ng * 2 + hf;
                    mma_bf16(s[nt], qh[kk], &kh[ng][hf * 2]);
                    mma_bf16(s[nt], ql[kk], &kh[ng][hf * 2]);
                    mma_bf16(s[nt], qh[kk], &kl[ng][hf * 2]);
                }
        }

        // scale
#pragma unroll
        for (int nt = 0; nt < 8; nt++)
#pragma unroll
            for (int c = 0; c < 4; c++) s[nt][c] *= 0.125f;

        if (anyzero) {
#pragma unroll
            for (int nt = 0; nt < 8; nt++) {
                const int col = j0 + nt * 8 + lc;
                if (mask[(size_t)r0 * SS + col] == 0)     s[nt][0] = -1e30f;
                if (mask[(size_t)r0 * SS + col + 1] == 0) s[nt][1] = -1e30f;
                if (mask[(size_t)r1 * SS + col] == 0)     s[nt][2] = -1e30f;
                if (mask[(size_t)r1 * SS + col + 1] == 0) s[nt][3] = -1e30f;
            }
        }

        // ---- online softmax on 16x64 strip ----
        float tm0 = s[0][0], tm1 = s[0][2];
#pragma unroll
        for (int nt = 0; nt < 8; nt++) {
            tm0 = fmaxf(tm0, fmaxf(s[nt][0], s[nt][1]));
            tm1 = fmaxf(tm1, fmaxf(s[nt][2], s[nt][3]));
        }
        tm0 = fmaxf(tm0, __shfl_xor_sync(0xffffffffu, tm0, 1));
        tm0 = fmaxf(tm0, __shfl_xor_sync(0xffffffffu, tm0, 2));
        tm1 = fmaxf(tm1, __shfl_xor_sync(0xffffffffu, tm1, 1));
        tm1 = fmaxf(tm1, __shfl_xor_sync(0xffffffffu, tm1, 2));

        const float mn0 = fmaxf(mrow0, tm0);
        const float mn1 = fmaxf(mrow1, tm1);
        const float corr0 = __expf(mrow0 - mn0);
        const float corr1 = __expf(mrow1 - mn1);
        mrow0 = mn0; mrow1 = mn1;

        float sum0 = 0.0f, sum1 = 0.0f;
        unsigned pa[4][4];
#pragma unroll
        for (int kk2 = 0; kk2 < 4; kk2++) {
            const int na = 2 * kk2, nb = 2 * kk2 + 1;
            const float pa00 = __expf(s[na][0] - mn0), pa01 = __expf(s[na][1] - mn0);
            const float pa10 = __expf(s[na][2] - mn1), pa11 = __expf(s[na][3] - mn1);
            const float pb00 = __expf(s[nb][0] - mn0), pb01 = __expf(s[nb][1] - mn0);
            const float pb10 = __expf(s[nb][2] - mn1), pb11 = __expf(s[nb][3] - mn1);
            sum0 += pa00 + pa01 + pb00 + pb01;
            sum1 += pa10 + pa11 + pb10 + pb11;
            pa[kk2][0] = packbf2(pa00, pa01);
            pa[kk2][1] = packbf2(pa10, pa11);
            pa[kk2][2] = packbf2(pb00, pb01);
            pa[kk2][3] = packbf2(pb10, pb11);
        }
        sum0 += __shfl_xor_sync(0xffffffffu, sum0, 1);
        sum0 += __shfl_xor_sync(0xffffffffu, sum0, 2);
        sum1 += __shfl_xor_sync(0xffffffffu, sum1, 1);
        sum1 += __shfl_xor_sync(0xffffffffu, sum1, 2);
        lrow0 = lrow0 * corr0 + sum0;
        lrow1 = lrow1 * corr1 + sum1;

#pragma unroll
        for (int nt = 0; nt < 8; nt++) {
            o[nt][0] *= corr0; o[nt][1] *= corr0;
            o[nt][2] *= corr1; o[nt][3] *= corr1;
        }

        // ---- O += P V  (bf16 P, bf16 V via ldmatrix.trans) ----
#pragma unroll
        for (int kk2 = 0; kk2 < 4; kk2++) {
#pragma unroll
            for (int dg = 0; dg < 4; dg++) {
                unsigned vt[4];
                ldsm4t(vt, vBase + kk2 * 16 * ROWB + dg * 32);
                mma_bf16s(o[dg * 2],     pa[kk2], vt[0], vt[2]);
                mma_bf16s(o[dg * 2 + 1], pa[kk2], vt[1], vt[3]);
            }
        }
    }

    const float invl0 = (mrow0 > -1e28f && lrow0 > 0.0f) ? (OMALPHA / lrow0) : 0.0f;
    const float invl1 = (mrow1 > -1e28f && lrow1 > 0.0f) ? (OMALPHA / lrow1) : 0.0f;

#pragma unroll
    for (int nt = 0; nt < 8; nt++) {
        const int d = h * 64 + nt * 8 + lc;
        float2* p0 = (float2*)&out[(size_t)(b * SS + r0) * DD + d];
        float2* p1 = (float2*)&out[(size_t)(b * SS + r1) * DD + d];
        float2 v0 = *p0, v1 = *p1;
        v0.x += o[nt][0] * invl0; v0.y += o[nt][1] * invl0;
        v1.x += o[nt][2] * invl1; v1.y += o[nt][3] * invl1;
        *p0 = v0; *p1 = v1;
    }
}

// ---------------------------------------------------------------------------
extern "C" void kernel_launch(void* const* d_in, const int* in_sizes, int n_in,
                              void* d_out, int out_size) {
    const float* x       = (const float*)d_in[0];
    const int*   mask    = (const int*)d_in[1];
    const float* sb      = (const float*)d_in[2];
    const float* gamma   = (const float*)d_in[3];
    const float* lnb     = (const float*)d_in[4];
    const float* qw      = (const float*)d_in[5];
    const float* qb      = (const float*)d_in[6];
    const float* kw      = (const float*)d_in[7];
    const float* kb      = (const float*)d_in[8];
    const float* vw      = (const float*)d_in[9];
    const float* vb      = (const float*)d_in[10];
    float* out = (float*)d_out;
    const int maskN = in_sizes[1];

    __nv_bfloat16 *xhi = nullptr, *xlo = nullptr, *whi = nullptr, *wlo = nullptr;
    cudaGetSymbolAddress((void**)&xhi, g_Xhi);
    cudaGetSymbolAddress((void**)&xlo, g_Xlo);
    cudaGetSymbolAddress((void**)&whi, g_Whi);
    cudaGetSymbolAddress((void**)&wlo, g_Wlo);

    const int nX4 = BB * SS * DD / 4;
    const int nW4 = DD * DD / 4;
    split_kernel<<<(nX4 + 255) / 256, 256>>>(x, xhi, xlo, nX4);
    split_kernel<<<(nW4 + 255) / 256, 256>>>(qw, whi, wlo, nW4);
    split_kernel<<<(nW4 + 255) / 256, 256>>>(kw, whi + (size_t)DD * DD, wlo + (size_t)DD * DD, nW4);
    split_kernel<<<(nW4 + 255) / 256, 256>>>(vw, whi + (size_t)2 * DD * DD, wlo + (size_t)2 * DD * DD, nW4);

    zero_scratch_kernel<<<(BB * DD * 5 + 255) / 256, 256>>>();
    fourier_stats_kernel<<<dim3(16, BB), 256>>>(x);
    mask_scan_kernel<<<512, 256>>>(mask, maskN);
    dsp_ln_kernel<<<BB * SS, 256>>>(x, sb, gamma, lnb, out);
    gemm_qkv_mma<<<dim3(DD / BN, BB * SS / BM, 3), 256>>>(qb, kb, vb);
    attn_mma_kernel<<<dim3(SS / 128, BB * HH), 256>>>(mask, out);
}

// round 6
// speedup vs baseline: 6.7804x; 1.8430x over previous
#include <cuda_runtime.h>
#include <cuda_bf16.h>
#include <math.h>
#include <float.h>

// Problem constants
#define BB 4
#define SS 2048
#define DD 1024
#define HH 16
#define DK 64
#define ALPHA 0.7f
#define OMALPHA 0.3f

// GEMM tile
#define BM 128
#define BN 128
#define BKK 32
#define SROW 40   // padded smem row in bf16 (80B)
#define GEMM_BUFB (BM * SROW * 2)   // bytes per smem buffer (10240)

// Attention smem row stride (64 data + 8 pad)
#define VROW 72
#define ATT_BUFB (64 * VROW * 2)    // 9216 bytes per tensor buffer

// Scratch (device globals; allocation-free per harness rules)
__device__ float g_stats[BB * DD * 5];
__device__ int   g_anymaskzero;

__device__ __nv_bfloat16 g_Xh[BB * SS * DD];
__device__ __nv_bfloat16 g_Wh[3 * DD * DD];
__device__ __nv_bfloat16 g_Qh[BB * SS * DD];
__device__ __nv_bfloat16 g_Kh[BB * SS * DD];
__device__ __nv_bfloat16 g_Vh[BB * SS * DD];

// ---- mma / async helpers ----
__device__ __forceinline__ unsigned sptr(const void* p) {
    return (unsigned)__cvta_generic_to_shared(p);
}
__device__ __forceinline__ void ldsm4(unsigned* r, unsigned addr) {
    asm volatile("ldmatrix.sync.aligned.m8n8.x4.shared.b16 {%0,%1,%2,%3}, [%4];\n"
                 : "=r"(r[0]), "=r"(r[1]), "=r"(r[2]), "=r"(r[3]) : "r"(addr));
}
__device__ __forceinline__ void ldsm4t(unsigned* r, unsigned addr) {
    asm volatile("ldmatrix.sync.aligned.m8n8.x4.trans.shared.b16 {%0,%1,%2,%3}, [%4];\n"
                 : "=r"(r[0]), "=r"(r[1]), "=r"(r[2]), "=r"(r[3]) : "r"(addr));
}
__device__ __forceinline__ void mma_bf16(float* c, const unsigned* a, const unsigned* b) {
    asm volatile("mma.sync.aligned.m16n8k16.row.col.f32.bf16.bf16.f32 "
                 "{%0,%1,%2,%3}, {%4,%5,%6,%7}, {%8,%9}, {%0,%1,%2,%3};\n"
                 : "+f"(c[0]), "+f"(c[1]), "+f"(c[2]), "+f"(c[3])
                 : "r"(a[0]), "r"(a[1]), "r"(a[2]), "r"(a[3]), "r"(b[0]), "r"(b[1]));
}
__device__ __forceinline__ void mma_bf16s(float* c, const unsigned* a, unsigned b0, unsigned b1) {
    asm volatile("mma.sync.aligned.m16n8k16.row.col.f32.bf16.bf16.f32 "
                 "{%0,%1,%2,%3}, {%4,%5,%6,%7}, {%8,%9}, {%0,%1,%2,%3};\n"
                 : "+f"(c[0]), "+f"(c[1]), "+f"(c[2]), "+f"(c[3])
                 : "r"(a[0]), "r"(a[1]), "r"(a[2]), "r"(a[3]), "r"(b0), "r"(b1));
}
__device__ __forceinline__ unsigned packbf2(float lo, float hi) {
    __nv_bfloat162 v = __floats2bfloat162_rn(lo, hi);
    return *(unsigned*)&v;
}
__device__ __forceinline__ void cpasync16(unsigned dst, const void* src) {
    asm volatile("cp.async.cg.shared.global [%0], [%1], 16;\n" :: "r"(dst), "l"(src));
}
__device__ __forceinline__ void cpcommit() {
    asm volatile("cp.async.commit_group;\n");
}
template<int N> __device__ __forceinline__ void cpwait() {
    asm volatile("cp.async.wait_group %0;\n" :: "n"(N));
}

// ---------------------------------------------------------------------------
// Kernel 0: zero scratch stats + mask flag
// ---------------------------------------------------------------------------
__global__ void zero_scratch_kernel() {
    int i = blockIdx.x * blockDim.x + threadIdx.x;
    if (i < BB * DD * 5) g_stats[i] = 0.0f;
    if (i == 0) g_anymaskzero = 0;
}

// ---------------------------------------------------------------------------
// fp32 -> bf16 convert
// ---------------------------------------------------------------------------
__global__ void tobf16_kernel(const float* __restrict__ src,
                              __nv_bfloat16* __restrict__ dst, int n4) {
    int i = blockIdx.x * blockDim.x + threadIdx.x;
    if (i >= n4) return;
    float4 v = ((const float4*)src)[i];
    __nv_bfloat162* dp = (__nv_bfloat162*)dst;
    dp[2 * i]     = __floats2bfloat162_rn(v.x, v.y);
    dp[2 * i + 1] = __floats2bfloat162_rn(v.z, v.w);
}

// ---------------------------------------------------------------------------
// Kernel 1: Fourier stats
// ---------------------------------------------------------------------------
__global__ void fourier_stats_kernel(const float* __restrict__ x) {
    const int b = blockIdx.y;
    const int sc = blockIdx.x;
    const int tid = threadIdx.x;
    const float w0 = 6.283185307179586476925286766559f / (float)SS;

    float acc[4][5];
#pragma unroll
    for (int i = 0; i < 4; i++)
#pragma unroll
        for (int k = 0; k < 5; k++) acc[i][k] = 0.0f;

    for (int si = 0; si < SS / 16; si++) {
        const int s = sc * (SS / 16) + si;
        float s1, c1;
        sincosf(w0 * (float)s, &s1, &c1);
        const float c2 = c1 * c1 - s1 * s1;
        const float s2 = 2.0f * s1 * c1;
        const float* xp = x + ((size_t)(b * SS + s)) * DD + tid;
#pragma unroll
        for (int i = 0; i < 4; i++) {
            const float v = xp[i * 256];
            acc[i][0] += v;
            acc[i][1] += v * c1;
            acc[i][2] += v * s1;
            acc[i][3] += v * c2;
            acc[i][4] += v * s2;
        }
    }
#pragma unroll
    for (int i = 0; i < 4; i++) {
        const int d = i * 256 + tid;
        float* st = &g_stats[(b * DD + d) * 5];
        atomicAdd(&st[0], acc[i][0]);
        atomicAdd(&st[1], acc[i][1]);
        atomicAdd(&st[2], acc[i][2]);
        atomicAdd(&st[3], acc[i][3]);
        atomicAdd(&st[4], acc[i][4]);
    }
}

// ---------------------------------------------------------------------------
// Kernel 2: mask scan
// ---------------------------------------------------------------------------
__global__ void mask_scan_kernel(const int* __restrict__ mask, int n) {
    int i = blockIdx.x * blockDim.x + threadIdx.x;
    const int stride = gridDim.x * blockDim.x;
    bool z = false;
    for (; i < n; i += stride)
        if (mask[i] == 0) z = true;
    if (z) atomicExch(&g_anymaskzero, 1);
}

// ---------------------------------------------------------------------------
// Kernel 3: DSP branch + LayerNorm -> ALPHA*dsp into out
// ---------------------------------------------------------------------------
__global__ void dsp_ln_kernel(const float* __restrict__ x,
                              const float* __restrict__ sqrt_beta,
                              const float* __restrict__ gamma,
                              const float* __restrict__ lnb,
                              float* __restrict__ out) {
    const int bt = blockIdx.x;
    const int b = bt >> 11;
    const int t = bt & (SS - 1);
    const int tid = threadIdx.x;
    const float w0 = 6.283185307179586476925286766559f / (float)SS;

    float s1, c1;
    sincosf(w0 * (float)t, &s1, &c1);
    const float c2 = c1 * c1 - s1 * s1;
    const float s2 = 2.0f * s1 * c1;

    float y[4];
    float sum = 0.0f, sq = 0.0f;
#pragma unroll
    for (int i = 0; i < 4; i++) {
        const int d = i * 256 + tid;
        const float* st = &g_stats[(b * DD + d) * 5];
        const float lp = (st[0] + 2.0f * (st[1] * c1 + st[2] * s1)
                                + 2.0f * (st[3] * c2 + st[4] * s2)) * (1.0f / (float)SS);
        const float v = x[((size_t)(b * SS + t)) * DD + d];
        const float be = sqrt_beta[d];
        const float b2 = be * be;
        const float yy = (1.0f + b2) * v + (1.0f - b2) * lp;
        y[i] = yy;
        sum += yy;
        sq += yy * yy;
    }

    __shared__ float red[18];
#pragma unroll
    for (int o = 16; o; o >>= 1) {
        sum += __shfl_down_sync(0xffffffffu, sum, o);
        sq  += __shfl_down_sync(0xffffffffu, sq, o);
    }
    const int w = tid >> 5, ln = tid & 31;
    if (ln == 0) { red[w] = sum; red[w + 8] = sq; }
    __syncthreads();
    if (tid == 0) {
        float s = 0.0f, ssq = 0.0f;
        for (int i = 0; i < 8; i++) { s += red[i]; ssq += red[i + 8]; }
        red[16] = s; red[17] = ssq;
    }
    __syncthreads();
    sum = red[16]; sq = red[17];

    const float mu = sum * (1.0f / (float)DD);
    const float var = sq * (1.0f / (float)DD) - mu * mu;
    const float rs = rsqrtf(var + 1e-12f);
#pragma unroll
    for (int i = 0; i < 4; i++) {
        const int d = i * 256 + tid;
        out[((size_t)(b * SS + t)) * DD + d] =
            ALPHA * ((y[i] - mu) * rs * gamma[d] + lnb[d]);
    }
}

// ---------------------------------------------------------------------------
// Kernel 4: QKV GEMM, single-pass bf16 mma, cp.async double-buffered.
// C[m,n] = sum_k X[m,k]*W[n,k] + bias[n] -> bf16.
// ---------------------------------------------------------------------------
__global__ __launch_bounds__(256) void gemm_qkv_mma(
    const float* __restrict__ qb, const float* __restrict__ kb,
    const float* __restrict__ vb) {
    const int z = blockIdx.z;
    const __nv_bfloat16* W = g_Wh + (size_t)z * DD * DD;
    const float* bias;
    __nv_bfloat16* ohi;
    if (z == 0)      { bias = qb; ohi = g_Qh; }
    else if (z == 1) { bias = kb; ohi = g_Kh; }
    else             { bias = vb; ohi = g_Vh; }

    __shared__ __nv_bfloat16 sA[2][BM][SROW];
    __shared__ __nv_bfloat16 sB[2][BN][SROW];

    const int tid = threadIdx.x;
    const int lane = tid & 31, warp = tid >> 5;
    const int wm = warp & 1, wn = warp >> 1;
    const int m0 = blockIdx.y * BM, n0 = blockIdx.x * BN;

    float acc[4][4][4];
#pragma unroll
    for (int a = 0; a < 4; a++)
#pragma unroll
        for (int b = 0; b < 4; b++)
#pragma unroll
            for (int c = 0; c < 4; c++) acc[a][b][c] = 0.0f;

    const int grow = tid >> 1;
    const int gcol = (tid & 1) * 16;
    const __nv_bfloat16* pA = g_Xh + (size_t)(m0 + grow) * DD + gcol;
    const __nv_bfloat16* pB = W + (size_t)(n0 + grow) * DD + gcol;

    const unsigned dA0 = sptr(&sA[0][grow][gcol]);
    const unsigned dB0 = sptr(&sB[0][grow][gcol]);

    const unsigned aBase = sptr(&sA[0][wm * 64 + (lane & 15)][(lane >> 4) * 8]);
    const int j = lane >> 3;
    const unsigned bBase = sptr(&sB[0][wn * 32 + (j >> 1) * 8 + (lane & 7)][(j & 1) * 8]);
    const unsigned ROWB = SROW * 2;

    // prologue: tile 0 -> buffer 0
    cpasync16(dA0, pA);       cpasync16(dA0 + 16, pA + 8);
    cpasync16(dB0, pB);       cpasync16(dB0 + 16, pB + 8);
    cpcommit();

    for (int kb2 = 0, it = 0; kb2 < DD; kb2 += BKK, it++) {
        const int buf = it & 1;
        if (kb2 + BKK < DD) {
            const unsigned off = (buf ^ 1) * GEMM_BUFB;
            const int kn = kb2 + BKK;
            cpasync16(dA0 + off, pA + kn);  cpasync16(dA0 + off + 16, pA + kn + 8);
            cpasync16(dB0 + off, pB + kn);  cpasync16(dB0 + off + 16, pB + kn + 8);
            cpcommit();
            cpwait<1>();
        } else {
            cpwait<0>();
        }
        __syncthreads();

        const unsigned coff = buf * GEMM_BUFB;
#pragma unroll
        for (int ks = 0; ks < 2; ks++) {
            unsigned a[4][4], b[2][4];
#pragma unroll
            for (int mt = 0; mt < 4; mt++)
                ldsm4(a[mt], aBase + coff + mt * 16 * ROWB + ks * 32);
#pragma unroll
            for (int np = 0; np < 2; np++)
                ldsm4(b[np], bBase + coff + np * 16 * ROWB + ks * 32);
#pragma unroll
            for (int mt = 0; mt < 4; mt++)
#pragma unroll
                for (int nt = 0; nt < 4; nt++)
                    mma_bf16(acc[mt][nt], a[mt], &b[nt >> 1][(nt & 1) * 2]);
        }
        __syncthreads();
    }

    // epilogue: bias + bf16 store
#pragma unroll
    for (int nt = 0; nt < 4; nt++) {
        const int col = n0 + wn * 32 + nt * 8 + (lane & 3) * 2;
        const float bx = bias[col], by = bias[col + 1];
#pragma unroll
        for (int mt = 0; mt < 4; mt++) {
            const int r = m0 + wm * 64 + mt * 16 + (lane >> 2);
            *(__nv_bfloat162*)&ohi[(size_t)r * DD + col] =
                __floats2bfloat162_rn(acc[mt][nt][0] + bx, acc[mt][nt][1] + by);
            *(__nv_bfloat162*)&ohi[(size_t)(r + 8) * DD + col] =
                __floats2bfloat162_rn(acc[mt][nt][2] + bx, acc[mt][nt][3] + by);
        }
    }
}

// ---------------------------------------------------------------------------
// Kernel 5: tensor-core flash attention, single-pass bf16, cp.async pipelined.
// grid (SS/128, B*H), 256 threads (8 warps), 16 q-rows per warp.
// ---------------------------------------------------------------------------
__global__ __launch_bounds__(256, 1) void attn_mma_kernel(
    const int* __restrict__ mask, float* __restrict__ out) {
    const int qt = blockIdx.x;
    const int bh = blockIdx.y;
    const int b = bh >> 4, h = bh & 15;
    const int tid = threadIdx.x;
    const int lane = tid & 31, warp = tid >> 5;

    __shared__ __nv_bfloat16 sK[2][64 * VROW];
    __shared__ __nv_bfloat16 sV[2][64 * VROW];

    const int m0 = qt * 128 + warp * 16;
    const int r0 = m0 + (lane >> 2);
    const int r1 = r0 + 8;
    const int lc = (lane & 3) * 2;

    // Q fragments direct from gmem (fixed for whole kernel)
    unsigned qh[4][4];
#pragma unroll
    for (int kk = 0; kk < 4; kk++) {
        const int dbase = h * 64 + kk * 16 + lc;
        qh[kk][0] = *(const unsigned*)&g_Qh[(size_t)(b * SS + r0) * DD + dbase];
        qh[kk][1] = *(const unsigned*)&g_Qh[(size_t)(b * SS + r1) * DD + dbase];
        qh[kk][2] = *(const unsigned*)&g_Qh[(size_t)(b * SS + r0) * DD + dbase + 8];
        qh[kk][3] = *(const unsigned*)&g_Qh[(size_t)(b * SS + r1) * DD + dbase + 8];
    }

    float o[8][4];
#pragma unroll
    for (int nt = 0; nt < 8; nt++)
#pragma unroll
        for (int c = 0; c < 4; c++) o[nt][c] = 0.0f;
    float mrow0 = -1e30f, mrow1 = -1e30f;
    float lrow0 = 0.0f, lrow1 = 0.0f;

    const int anyzero = g_anymaskzero;

    // per-thread gmem->smem mapping: 2 x 16B per tensor per tile
    const int row0 = tid >> 3;            // rows 0..31
    const int c8   = (tid & 7) * 8;
    const unsigned sKd = sptr(&sK[0][row0 * VROW + c8]);
    const unsigned sVd = sptr(&sV[0][row0 * VROW + c8]);
    const unsigned rowStrideB = 32 * VROW * 2;   // +32 rows in bytes

    const int j = lane >> 3;
    const unsigned bRowCol = ((unsigned)((j >> 1) * 8 + (lane & 7))) * (VROW * 2) + (j & 1) * 16;
    const unsigned kBase = sptr(sK) + bRowCol;
    const unsigned vBase = sptr(sV) + bRowCol;
    const unsigned ROWB = VROW * 2;

    // prologue: tile 0 -> buffer 0
    {
        const size_t g0 = (size_t)(b * SS + row0) * DD + h * 64 + c8;
        cpasync16(sKd, &g_Kh[g0]);
        cpasync16(sKd + rowStrideB, &g_Kh[g0 + (size_t)32 * DD]);
        cpasync16(sVd, &g_Vh[g0]);
        cpasync16(sVd + rowStrideB, &g_Vh[g0 + (size_t)32 * DD]);
        cpcommit();
    }

    for (int kt = 0; kt < SS / 64; kt++) {
        const int buf = kt & 1;
        if (kt + 1 < SS / 64) {
            const unsigned off = (buf ^ 1) * ATT_BUFB;
            const size_t gn = (size_t)(b * SS + (kt + 1) * 64 + row0) * DD + h * 64 + c8;
            cpasync16(sKd + off, &g_Kh[gn]);
            cpasync16(sKd + off + rowStrideB, &g_Kh[gn + (size_t)32 * DD]);
            cpasync16(sVd + off, &g_Vh[gn]);
            cpasync16(sVd + off + rowStrideB, &g_Vh[gn + (size_t)32 * DD]);
            cpcommit();
            cpwait<1>();
        } else {
            cpwait<0>();
        }
        __syncthreads();

        const unsigned coff = buf * ATT_BUFB;
        const int j0 = kt * 64;

        // ---- S = Q K^T (single-pass bf16) ----
        float s[8][4];
#pragma unroll
        for (int nt = 0; nt < 8; nt++)
#pragma unroll
            for (int c = 0; c < 4; c++) s[nt][c] = 0.0f;

#pragma unroll
        for (int kk = 0; kk < 4; kk++) {
            unsigned kh[4][4];
#pragma unroll
            for (int ng = 0; ng < 4; ng++)
                ldsm4(kh[ng], kBase + coff + ng * 16 * ROWB + kk * 32);
#pragma unroll
            for (int ng = 0; ng < 4; ng++) {
                mma_bf16(s[ng * 2],     qh[kk], &kh[ng][0]);
                mma_bf16(s[ng * 2 + 1], qh[kk], &kh[ng][2]);
            }
        }

#pragma unroll
        for (int nt = 0; nt < 8; nt++)
#pragma unroll
            for (int c = 0; c < 4; c++) s[nt][c] *= 0.125f;

        if (anyzero) {
#pragma unroll
            for (int nt = 0; nt < 8; nt++) {
                const int col = j0 + nt * 8 + lc;
                if (mask[(size_t)r0 * SS + col] == 0)     s[nt][0] = -1e30f;
                if (mask[(size_t)r0 * SS + col + 1] == 0) s[nt][1] = -1e30f;
                if (mask[(size_t)r1 * SS + col] == 0)     s[nt][2] = -1e30f;
                if (mask[(size_t)r1 * SS + col + 1] == 0) s[nt][3] = -1e30f;
            }
        }

        // ---- online softmax on 16x64 strip ----
        float tm0 = s[0][0], tm1 = s[0][2];
#pragma unroll
        for (int nt = 0; nt < 8; nt++) {
            tm0 = fmaxf(tm0, fmaxf(s[nt][0], s[nt][1]));
            tm1 = fmaxf(tm1, fmaxf(s[nt][2], s[nt][3]));
        }
        tm0 = fmaxf(tm0, __shfl_xor_sync(0xffffffffu, tm0, 1));
        tm0 = fmaxf(tm0, __shfl_xor_sync(0xffffffffu, tm0, 2));
        tm1 = fmaxf(tm1, __shfl_xor_sync(0xffffffffu, tm1, 1));
        tm1 = fmaxf(tm1, __shfl_xor_sync(0xffffffffu, tm1, 2));

        const float mn0 = fmaxf(mrow0, tm0);
        const float mn1 = fmaxf(mrow1, tm1);
        const float corr0 = __expf(mrow0 - mn0);
        const float corr1 = __expf(mrow1 - mn1);
        mrow0 = mn0; mrow1 = mn1;

        float sum0 = 0.0f, sum1 = 0.0f;
        unsigned pa[4][4];
#pragma unroll
        for (int kk2 = 0; kk2 < 4; kk2++) {
            const int na = 2 * kk2, nb = 2 * kk2 + 1;
            const float pa00 = __expf(s[na][0] - mn0), pa01 = __expf(s[na][1] - mn0);
            const float pa10 = __expf(s[na][2] - mn1), pa11 = __expf(s[na][3] - mn1);
            const float pb00 = __expf(s[nb][0] - mn0), pb01 = __expf(s[nb][1] - mn0);
            const float pb10 = __expf(s[nb][2] - mn1), pb11 = __expf(s[nb][3] - mn1);
            sum0 += pa00 + pa01 + pb00 + pb01;
            sum1 += pa10 + pa11 + pb10 + pb11;
            pa[kk2][0] = packbf2(pa00, pa01);
            pa[kk2][1] = packbf2(pa10, pa11);
            pa[kk2][2] = packbf2(pb00, pb01);
            pa[kk2][3] = packbf2(pb10, pb11);
        }
        sum0 += __shfl_xor_sync(0xffffffffu, sum0, 1);
        sum0 += __shfl_xor_sync(0xffffffffu, sum0, 2);
        sum1 += __shfl_xor_sync(0xffffffffu, sum1, 1);
        sum1 += __shfl_xor_sync(0xffffffffu, sum1, 2);
        lrow0 = lrow0 * corr0 + sum0;
        lrow1 = lrow1 * corr1 + sum1;

#pragma unroll
        for (int nt = 0; nt < 8; nt++) {
            o[nt][0] *= corr0; o[nt][1] *= corr0;
            o[nt][2] *= corr1; o[nt][3] *= corr1;
        }

        // ---- O += P V ----
#pragma unroll
        for (int kk2 = 0; kk2 < 4; kk2++) {
#pragma unroll
            for (int dg = 0; dg < 4; dg++) {
                unsigned vt[4];
                ldsm4t(vt, vBase + coff + kk2 * 16 * ROWB + dg * 32);
                mma_bf16s(o[dg * 2],     pa[kk2], vt[0], vt[2]);
                mma_bf16s(o[dg * 2 + 1], pa[kk2], vt[1], vt[3]);
            }
        }
        __syncthreads();
    }

    const float invl0 = (mrow0 > -1e28f && lrow0 > 0.0f) ? (OMALPHA / lrow0) : 0.0f;
    const float invl1 = (mrow1 > -1e28f && lrow1 > 0.0f) ? (OMALPHA / lrow1) : 0.0f;

#pragma unroll
    for (int nt = 0; nt < 8; nt++) {
        const int d = h * 64 + nt * 8 + lc;
        float2* p0 = (float2*)&out[(size_t)(b * SS + r0) * DD + d];
        float2* p1 = (float2*)&out[(size_t)(b * SS + r1) * DD + d];
        float2 v0 = *p0, v1 = *p1;
        v0.x += o[nt][0] * invl0; v0.y += o[nt][1] * invl0;
        v1.x += o[nt][2] * invl1; v1.y += o[nt][3] * invl1;
        *p0 = v0; *p1 = v1;
    }
}

// ---------------------------------------------------------------------------
extern "C" void kernel_launch(void* const* d_in, const int* in_sizes, int n_in,
                              void* d_out, int out_size) {
    const float* x       = (const float*)d_in[0];
    const int*   mask    = (const int*)d_in[1];
    const float* sb      = (const float*)d_in[2];
    const float* gamma   = (const float*)d_in[3];
    const float* lnb     = (const float*)d_in[4];
    const float* qw      = (const float*)d_in[5];
    const float* qb      = (const float*)d_in[6];
    const float* kw      = (const float*)d_in[7];
    const float* kb      = (const float*)d_in[8];
    const float* vw      = (const float*)d_in[9];
    const float* vb      = (const float*)d_in[10];
    float* out = (float*)d_out;
    const int maskN = in_sizes[1];

    __nv_bfloat16 *xh = nullptr, *wh = nullptr;
    cudaGetSymbolAddress((void**)&xh, g_Xh);
    cudaGetSymbolAddress((void**)&wh, g_Wh);

    const int nX4 = BB * SS * DD / 4;
    const int nW4 = DD * DD / 4;
    tobf16_kernel<<<(nX4 + 255) / 256, 256>>>(x, xh, nX4);
    tobf16_kernel<<<(nW4 + 255) / 256, 256>>>(qw, wh, nW4);
    tobf16_kernel<<<(nW4 + 255) / 256, 256>>>(kw, wh + (size_t)DD * DD, nW4);
    tobf16_kernel<<<(nW4 + 255) / 256, 256>>>(vw, wh + (size_t)2 * DD * DD, nW4);

    zero_scratch_kernel<<<(BB * DD * 5 + 255) / 256, 256>>>();
    fourier_stats_kernel<<<dim3(16, BB), 256>>>(x);
    mask_scan_kernel<<<512, 256>>>(mask, maskN);
    dsp_ln_kernel<<<BB * SS, 256>>>(x, sb, gamma, lnb, out);
    gemm_qkv_mma<<<dim3(DD / BN, BB * SS / BM, 3), 256>>>(qb, kb, vb);
    attn_mma_kernel<<<dim3(SS / 128, BB * HH), 256>>>(mask, out);
}

// round 7
// speedup vs baseline: 7.7059x; 1.1365x over previous
#include <cuda_runtime.h>
#include <cuda_bf16.h>
#include <math.h>
#include <float.h>

// Problem constants
#define BB 4
#define SS 2048
#define DD 1024
#define HH 16
#define DK 64
#define ALPHA 0.7f
#define OMALPHA 0.3f

// GEMM tile
#define BM 128
#define BN 128
#define BKK 32
#define SROW 40                       // padded smem row in bf16 (80B)
#define GEMM_BUF (BM * SROW)          // bf16 elems per A (or B) buffer
#define GEMM_BUFB (GEMM_BUF * 2)      // 10240 bytes
#define GEMM_SMEM (3 * 2 * GEMM_BUFB) // 61440 bytes

// Attention
#define VROW 72
#define ATT_BUF (64 * VROW)           // bf16 elems per tensor buffer
#define ATT_BUFB (ATT_BUF * 2)        // 9216 bytes
#define ATT_SMEM (3 * 2 * ATT_BUFB)   // 55296 bytes
#define NTILES (SS / 64)              // 32

// Scratch (device globals; allocation-free per harness rules)
__device__ float g_stats[BB * DD * 5];
__device__ int   g_anymaskzero;

__device__ __nv_bfloat16 g_Xh[BB * SS * DD];
__device__ __nv_bfloat16 g_Wh[3 * DD * DD];
__device__ __nv_bfloat16 g_Qh[BB * SS * DD];
__device__ __nv_bfloat16 g_Kh[BB * SS * DD];
__device__ __nv_bfloat16 g_Vh[BB * SS * DD];

// ---- mma / async helpers ----
__device__ __forceinline__ unsigned sptr(const void* p) {
    return (unsigned)__cvta_generic_to_shared(p);
}
__device__ __forceinline__ void ldsm4(unsigned* r, unsigned addr) {
    asm volatile("ldmatrix.sync.aligned.m8n8.x4.shared.b16 {%0,%1,%2,%3}, [%4];\n"
                 : "=r"(r[0]), "=r"(r[1]), "=r"(r[2]), "=r"(r[3]) : "r"(addr));
}
__device__ __forceinline__ void ldsm4t(unsigned* r, unsigned addr) {
    asm volatile("ldmatrix.sync.aligned.m8n8.x4.trans.shared.b16 {%0,%1,%2,%3}, [%4];\n"
                 : "=r"(r[0]), "=r"(r[1]), "=r"(r[2]), "=r"(r[3]) : "r"(addr));
}
__device__ __forceinline__ void mma_bf16(float* c, const unsigned* a, const unsigned* b) {
    asm volatile("mma.sync.aligned.m16n8k16.row.col.f32.bf16.bf16.f32 "
                 "{%0,%1,%2,%3}, {%4,%5,%6,%7}, {%8,%9}, {%0,%1,%2,%3};\n"
                 : "+f"(c[0]), "+f"(c[1]), "+f"(c[2]), "+f"(c[3])
                 : "r"(a[0]), "r"(a[1]), "r"(a[2]), "r"(a[3]), "r"(b[0]), "r"(b[1]));
}
__device__ __forceinline__ void mma_bf16s(float* c, const unsigned* a, unsigned b0, unsigned b1) {
    asm volatile("mma.sync.aligned.m16n8k16.row.col.f32.bf16.bf16.f32 "
                 "{%0,%1,%2,%3}, {%4,%5,%6,%7}, {%8,%9}, {%0,%1,%2,%3};\n"
                 : "+f"(c[0]), "+f"(c[1]), "+f"(c[2]), "+f"(c[3])
                 : "r"(a[0]), "r"(a[1]), "r"(a[2]), "r"(a[3]), "r"(b0), "r"(b1));
}
__device__ __forceinline__ unsigned packbf2(float lo, float hi) {
    __nv_bfloat162 v = __floats2bfloat162_rn(lo, hi);
    return *(unsigned*)&v;
}
__device__ __forceinline__ void cpasync16(unsigned dst, const void* src) {
    asm volatile("cp.async.cg.shared.global [%0], [%1], 16;\n" :: "r"(dst), "l"(src));
}
__device__ __forceinline__ void cpcommit() {
    asm volatile("cp.async.commit_group;\n");
}
template<int N> __device__ __forceinline__ void cpwait() {
    asm volatile("cp.async.wait_group %0;\n" :: "n"(N));
}

// ---------------------------------------------------------------------------
// Kernel 0: zero scratch stats + mask flag
// ---------------------------------------------------------------------------
__global__ void zero_scratch_kernel() {
    int i = blockIdx.x * blockDim.x + threadIdx.x;
    if (i < BB * DD * 5) g_stats[i] = 0.0f;
    if (i == 0) g_anymaskzero = 0;
}

// ---------------------------------------------------------------------------
// fp32 -> bf16 convert
// ---------------------------------------------------------------------------
__global__ void tobf16_kernel(const float* __restrict__ src,
                              __nv_bfloat16* __restrict__ dst, int n4) {
    int i = blockIdx.x * blockDim.x + threadIdx.x;
    if (i >= n4) return;
    float4 v = ((const float4*)src)[i];
    __nv_bfloat162* dp = (__nv_bfloat162*)dst;
    dp[2 * i]     = __floats2bfloat162_rn(v.x, v.y);
    dp[2 * i + 1] = __floats2bfloat162_rn(v.z, v.w);
}

// ---------------------------------------------------------------------------
// Kernel 1: Fourier stats
// ---------------------------------------------------------------------------
__global__ void fourier_stats_kernel(const float* __restrict__ x) {
    const int b = blockIdx.y;
    const int sc = blockIdx.x;
    const int tid = threadIdx.x;
    const float w0 = 6.283185307179586476925286766559f / (float)SS;

    float acc[4][5];
#pragma unroll
    for (int i = 0; i < 4; i++)
#pragma unroll
        for (int k = 0; k < 5; k++) acc[i][k] = 0.0f;

    for (int si = 0; si < SS / 16; si++) {
        const int s = sc * (SS / 16) + si;
        float s1, c1;
        sincosf(w0 * (float)s, &s1, &c1);
        const float c2 = c1 * c1 - s1 * s1;
        const float s2 = 2.0f * s1 * c1;
        const float* xp = x + ((size_t)(b * SS + s)) * DD + tid;
#pragma unroll
        for (int i = 0; i < 4; i++) {
            const float v = xp[i * 256];
            acc[i][0] += v;
            acc[i][1] += v * c1;
            acc[i][2] += v * s1;
            acc[i][3] += v * c2;
            acc[i][4] += v * s2;
        }
    }
#pragma unroll
    for (int i = 0; i < 4; i++) {
        const int d = i * 256 + tid;
        float* st = &g_stats[(b * DD + d) * 5];
        atomicAdd(&st[0], acc[i][0]);
        atomicAdd(&st[1], acc[i][1]);
        atomicAdd(&st[2], acc[i][2]);
        atomicAdd(&st[3], acc[i][3]);
        atomicAdd(&st[4], acc[i][4]);
    }
}

// ---------------------------------------------------------------------------
// Kernel 2: mask scan
// ---------------------------------------------------------------------------
__global__ void mask_scan_kernel(const int* __restrict__ mask, int n) {
    int i = blockIdx.x * blockDim.x + threadIdx.x;
    const int stride = gridDim.x * blockDim.x;
    bool z = false;
    for (; i < n; i += stride)
        if (mask[i] == 0) z = true;
    if (z) atomicExch(&g_anymaskzero, 1);
}

// ---------------------------------------------------------------------------
// Kernel 3: DSP branch + LayerNorm -> ALPHA*dsp into out
// ---------------------------------------------------------------------------
__global__ void dsp_ln_kernel(const float* __restrict__ x,
                              const float* __restrict__ sqrt_beta,
                              const float* __restrict__ gamma,
                              const float* __restrict__ lnb,
                              float* __restrict__ out) {
    const int bt = blockIdx.x;
    const int b = bt >> 11;
    const int t = bt & (SS - 1);
    const int tid = threadIdx.x;
    const float w0 = 6.283185307179586476925286766559f / (float)SS;

    float s1, c1;
    sincosf(w0 * (float)t, &s1, &c1);
    const float c2 = c1 * c1 - s1 * s1;
    const float s2 = 2.0f * s1 * c1;

    float y[4];
    float sum = 0.0f, sq = 0.0f;
#pragma unroll
    for (int i = 0; i < 4; i++) {
        const int d = i * 256 + tid;
        const float* st = &g_stats[(b * DD + d) * 5];
        const float lp = (st[0] + 2.0f * (st[1] * c1 + st[2] * s1)
                                + 2.0f * (st[3] * c2 + st[4] * s2)) * (1.0f / (float)SS);
        const float v = x[((size_t)(b * SS + t)) * DD + d];
        const float be = sqrt_beta[d];
        const float b2 = be * be;
        const float yy = (1.0f + b2) * v + (1.0f - b2) * lp;
        y[i] = yy;
        sum += yy;
        sq += yy * yy;
    }

    __shared__ float red[18];
#pragma unroll
    for (int o = 16; o; o >>= 1) {
        sum += __shfl_down_sync(0xffffffffu, sum, o);
        sq  += __shfl_down_sync(0xffffffffu, sq, o);
    }
    const int w = tid >> 5, ln = tid & 31;
    if (ln == 0) { red[w] = sum; red[w + 8] = sq; }
    __syncthreads();
    if (tid == 0) {
        float s = 0.0f, ssq = 0.0f;
        for (int i = 0; i < 8; i++) { s += red[i]; ssq += red[i + 8]; }
        red[16] = s; red[17] = ssq;
    }
    __syncthreads();
    sum = red[16]; sq = red[17];

    const float mu = sum * (1.0f / (float)DD);
    const float var = sq * (1.0f / (float)DD) - mu * mu;
    const float rs = rsqrtf(var + 1e-12f);
#pragma unroll
    for (int i = 0; i < 4; i++) {
        const int d = i * 256 + tid;
        out[((size_t)(b * SS + t)) * DD + d] =
            ALPHA * ((y[i] - mu) * rs * gamma[d] + lnb[d]);
    }
}

// ---------------------------------------------------------------------------
// Kernel 4: QKV GEMM, bf16 mma, 3-stage cp.async pipeline, 1 sync/tile.
// Q output pre-scaled by 1/8 (folded attention score scale).
// ---------------------------------------------------------------------------
__global__ __launch_bounds__(256) void gemm_qkv_mma(
    const float* __restrict__ qb, const float* __restrict__ kb,
    const float* __restrict__ vb) {
    const int z = blockIdx.z;
    const __nv_bfloat16* W = g_Wh + (size_t)z * DD * DD;
    const float* bias;
    __nv_bfloat16* ohi;
    if (z == 0)      { bias = qb; ohi = g_Qh; }
    else if (z == 1) { bias = kb; ohi = g_Kh; }
    else             { bias = vb; ohi = g_Vh; }
    const float oscale = (z == 0) ? 0.125f : 1.0f;

    extern __shared__ char smem_dyn[];
    __nv_bfloat16* sA = (__nv_bfloat16*)smem_dyn;              // 3 x GEMM_BUF
    __nv_bfloat16* sB = sA + 3 * GEMM_BUF;                     // 3 x GEMM_BUF

    const int tid = threadIdx.x;
    const int lane = tid & 31, warp = tid >> 5;
    const int wm = warp & 1, wn = warp >> 1;
    const int m0 = blockIdx.y * BM, n0 = blockIdx.x * BN;

    float acc[4][4][4];
#pragma unroll
    for (int a = 0; a < 4; a++)
#pragma unroll
        for (int b = 0; b < 4; b++)
#pragma unroll
            for (int c = 0; c < 4; c++) acc[a][b][c] = 0.0f;

    const int grow = tid >> 1;
    const int gcol = (tid & 1) * 16;
    const __nv_bfloat16* pA = g_Xh + (size_t)(m0 + grow) * DD + gcol;
    const __nv_bfloat16* pB = W + (size_t)(n0 + grow) * DD + gcol;

    const unsigned dA0 = sptr(sA + grow * SROW + gcol);
    const unsigned dB0 = sptr(sB + grow * SROW + gcol);

    const unsigned aBase0 = sptr(sA) + ((unsigned)(wm * 64 + (lane & 15))) * (SROW * 2) + (lane >> 4) * 16;
    const int j = lane >> 3;
    const unsigned bBase0 = sptr(sB) + ((unsigned)(wn * 32 + (j >> 1) * 8 + (lane & 7))) * (SROW * 2) + (j & 1) * 16;
    const unsigned ROWB = SROW * 2;

    const int NT = DD / BKK;   // 32
    // prologue: tiles 0,1 -> bufs 0,1
#pragma unroll
    for (int p = 0; p < 2; p++) {
        const unsigned off = p * GEMM_BUFB;
        const int kk = p * BKK;
        cpasync16(dA0 + off, pA + kk);  cpasync16(dA0 + off + 16, pA + kk + 8);
        cpasync16(dB0 + off, pB + kk);  cpasync16(dB0 + off + 16, pB + kk + 8);
        cpcommit();
    }

    for (int it = 0; it < NT; it++) {
        if (it < NT - 1) cpwait<1>(); else cpwait<0>();
        __syncthreads();
        if (it + 2 < NT) {
            const unsigned off = ((it + 2) % 3) * GEMM_BUFB;
            const int kk = (it + 2) * BKK;
            cpasync16(dA0 + off, pA + kk);  cpasync16(dA0 + off + 16, pA + kk + 8);
            cpasync16(dB0 + off, pB + kk);  cpasync16(dB0 + off + 16, pB + kk + 8);
            cpcommit();
        }

        const unsigned coff = (it % 3) * GEMM_BUFB;
#pragma unroll
        for (int ks = 0; ks < 2; ks++) {
            unsigned a[4][4], b[2][4];
#pragma unroll
            for (int mt = 0; mt < 4; mt++)
                ldsm4(a[mt], aBase0 + coff + mt * 16 * ROWB + ks * 32);
#pragma unroll
            for (int np = 0; np < 2; np++)
                ldsm4(b[np], bBase0 + coff + np * 16 * ROWB + ks * 32);
#pragma unroll
            for (int mt = 0; mt < 4; mt++)
#pragma unroll
                for (int nt = 0; nt < 4; nt++)
                    mma_bf16(acc[mt][nt], a[mt], &b[nt >> 1][(nt & 1) * 2]);
        }
    }

    // epilogue: bias (+Q scale) + bf16 store
#pragma unroll
    for (int nt = 0; nt < 4; nt++) {
        const int col = n0 + wn * 32 + nt * 8 + (lane & 3) * 2;
        const float bx = bias[col], by = bias[col + 1];
#pragma unroll
        for (int mt = 0; mt < 4; mt++) {
            const int r = m0 + wm * 64 + mt * 16 + (lane >> 2);
            *(__nv_bfloat162*)&ohi[(size_t)r * DD + col] =
                __floats2bfloat162_rn((acc[mt][nt][0] + bx) * oscale,
                                      (acc[mt][nt][1] + by) * oscale);
            *(__nv_bfloat162*)&ohi[(size_t)(r + 8) * DD + col] =
                __floats2bfloat162_rn((acc[mt][nt][2] + bx) * oscale,
                                      (acc[mt][nt][3] + by) * oscale);
        }
    }
}

// ---------------------------------------------------------------------------
// Kernel 5: tensor-core flash attention, no-max softmax (shift-invariant,
// scores are O(1)-bounded), 3-stage cp.async pipeline, 1 sync/tile.
// grid (SS/128, B*H), 256 threads (8 warps), 16 q-rows per warp.
// ---------------------------------------------------------------------------
__global__ __launch_bounds__(256) void attn_mma_kernel(
    const int* __restrict__ mask, float* __restrict__ out) {
    const int qt = blockIdx.x;
    const int bh = blockIdx.y;
    const int b = bh >> 4, h = bh & 15;
    const int tid = threadIdx.x;
    const int lane = tid & 31, warp = tid >> 5;

    extern __shared__ char smem_dyn[];
    __nv_bfloat16* sK = (__nv_bfloat16*)smem_dyn;   // 3 x ATT_BUF
    __nv_bfloat16* sV = sK + 3 * ATT_BUF;           // 3 x ATT_BUF

    const int m0 = qt * 128 + warp * 16;
    const int r0 = m0 + (lane >> 2);
    const int r1 = r0 + 8;
    const int lc = (lane & 3) * 2;

    // Q fragments (already pre-scaled by 1/8 in GEMM epilogue)
    unsigned qh[4][4];
#pragma unroll
    for (int kk = 0; kk < 4; kk++) {
        const int dbase = h * 64 + kk * 16 + lc;
        qh[kk][0] = *(const unsigned*)&g_Qh[(size_t)(b * SS + r0) * DD + dbase];
        qh[kk][1] = *(const unsigned*)&g_Qh[(size_t)(b * SS + r1) * DD + dbase];
        qh[kk][2] = *(const unsigned*)&g_Qh[(size_t)(b * SS + r0) * DD + dbase + 8];
        qh[kk][3] = *(const unsigned*)&g_Qh[(size_t)(b * SS + r1) * DD + dbase + 8];
    }

    float o[8][4];
#pragma unroll
    for (int nt = 0; nt < 8; nt++)
#pragma unroll
        for (int c = 0; c < 4; c++) o[nt][c] = 0.0f;
    float lrow0 = 0.0f, lrow1 = 0.0f;   // lane-partial softmax denominators

    const int anyzero = g_anymaskzero;

    // gmem->smem mapping: 2 x 16B per tensor per tile per thread
    const int row0 = tid >> 3;            // rows 0..31
    const int c8   = (tid & 7) * 8;
    const unsigned sKd = sptr(sK + row0 * VROW + c8);
    const unsigned sVd = sptr(sV + row0 * VROW + c8);
    const unsigned rowStrideB = 32 * VROW * 2;

    const int j = lane >> 3;
    const unsigned bRowCol = ((unsigned)((j >> 1) * 8 + (lane & 7))) * (VROW * 2) + (j & 1) * 16;
    const unsigned kBase = sptr(sK) + bRowCol;
    const unsigned vBase = sptr(sV) + bRowCol;
    const unsigned ROWB = VROW * 2;

    // prologue: tiles 0,1 -> bufs 0,1
#pragma unroll
    for (int p = 0; p < 2; p++) {
        const unsigned off = p * ATT_BUFB;
        const size_t g0 = (size_t)(b * SS + p * 64 + row0) * DD + h * 64 + c8;
        cpasync16(sKd + off, &g_Kh[g0]);
        cpasync16(sKd + off + rowStrideB, &g_Kh[g0 + (size_t)32 * DD]);
        cpasync16(sVd + off, &g_Vh[g0]);
        cpasync16(sVd + off + rowStrideB, &g_Vh[g0 + (size_t)32 * DD]);
        cpcommit();
    }

    for (int kt = 0; kt < NTILES; kt++) {
        if (kt < NTILES - 1) cpwait<1>(); else cpwait<0>();
        __syncthreads();
        if (kt + 2 < NTILES) {
            const unsigned off = ((kt + 2) % 3) * ATT_BUFB;
            const size_t gn = (size_t)(b * SS + (kt + 2) * 64 + row0) * DD + h * 64 + c8;
            cpasync16(sKd + off, &g_Kh[gn]);
            cpasync16(sKd + off + rowStrideB, &g_Kh[gn + (size_t)32 * DD]);
            cpasync16(sVd + off, &g_Vh[gn]);
            cpasync16(sVd + off + rowStrideB, &g_Vh[gn + (size_t)32 * DD]);
            cpcommit();
        }

        const unsigned coff = (kt % 3) * ATT_BUFB;
        const int j0 = kt * 64;

        // ---- S = Q K^T (Q pre-scaled) ----
        float s[8][4];
#pragma unroll
        for (int nt = 0; nt < 8; nt++)
#pragma unroll
            for (int c = 0; c < 4; c++) s[nt][c] = 0.0f;

#pragma unroll
        for (int kk = 0; kk < 4; kk++) {
            unsigned kh[4][4];
#pragma unroll
            for (int ng = 0; ng < 4; ng++)
                ldsm4(kh[ng], kBase + coff + ng * 16 * ROWB + kk * 32);
#pragma unroll
            for (int ng = 0; ng < 4; ng++) {
                mma_bf16(s[ng * 2],     qh[kk], &kh[ng][0]);
                mma_bf16(s[ng * 2 + 1], qh[kk], &kh[ng][2]);
            }
        }

        if (anyzero) {
#pragma unroll
            for (int nt = 0; nt < 8; nt++) {
                const int col = j0 + nt * 8 + lc;
                if (mask[(size_t)r0 * SS + col] == 0)     s[nt][0] = -1e30f;
                if (mask[(size_t)r0 * SS + col + 1] == 0) s[nt][1] = -1e30f;
                if (mask[(size_t)r1 * SS + col] == 0)     s[nt][2] = -1e30f;
                if (mask[(size_t)r1 * SS + col + 1] == 0) s[nt][3] = -1e30f;
            }
        }

        // ---- p = exp(s) (no max shift: scores O(1)-bounded) ----
        unsigned pa[4][4];
#pragma unroll
        for (int kk2 = 0; kk2 < 4; kk2++) {
            const int na = 2 * kk2, nb = 2 * kk2 + 1;
            const float pa00 = __expf(s[na][0]), pa01 = __expf(s[na][1]);
            const float pa10 = __expf(s[na][2]), pa11 = __expf(s[na][3]);
            const float pb00 = __expf(s[nb][0]), pb01 = __expf(s[nb][1]);
            const float pb10 = __expf(s[nb][2]), pb11 = __expf(s[nb][3]);
            lrow0 += pa00 + pa01 + pb00 + pb01;
            lrow1 += pa10 + pa11 + pb10 + pb11;
            pa[kk2][0] = packbf2(pa00, pa01);
            pa[kk2][1] = packbf2(pa10, pa11);
            pa[kk2][2] = packbf2(pb00, pb01);
            pa[kk2][3] = packbf2(pb10, pb11);
        }

        // ---- O += P V ----
#pragma unroll
        for (int kk2 = 0; kk2 < 4; kk2++) {
#pragma unroll
            for (int dg = 0; dg < 4; dg++) {
                unsigned vt[4];
                ldsm4t(vt, vBase + coff + kk2 * 16 * ROWB + dg * 32);
                mma_bf16s(o[dg * 2],     pa[kk2], vt[0], vt[2]);
                mma_bf16s(o[dg * 2 + 1], pa[kk2], vt[1], vt[3]);
            }
        }
    }

    // final denominator reduction across the quad
    lrow0 += __shfl_xor_sync(0xffffffffu, lrow0, 1);
    lrow0 += __shfl_xor_sync(0xffffffffu, lrow0, 2);
    lrow1 += __shfl_xor_sync(0xffffffffu, lrow1, 1);
    lrow1 += __shfl_xor_sync(0xffffffffu, lrow1, 2);

    const float invl0 = (lrow0 > 0.0f) ? (OMALPHA / lrow0) : 0.0f;
    const float invl1 = (lrow1 > 0.0f) ? (OMALPHA / lrow1) : 0.0f;

#pragma unroll
    for (int nt = 0; nt < 8; nt++) {
        const int d = h * 64 + nt * 8 + lc;
        float2* p0 = (float2*)&out[(size_t)(b * SS + r0) * DD + d];
        float2* p1 = (float2*)&out[(size_t)(b * SS + r1) * DD + d];
        float2 v0 = *p0, v1 = *p1;
        v0.x += o[nt][0] * invl0; v0.y += o[nt][1] * invl0;
        v1.x += o[nt][2] * invl1; v1.y += o[nt][3] * invl1;
        *p0 = v0; *p1 = v1;
    }
}

// ---------------------------------------------------------------------------
extern "C" void kernel_launch(void* const* d_in, const int* in_sizes, int n_in,
                              void* d_out, int out_size) {
    const float* x       = (const float*)d_in[0];
    const int*   mask    = (const int*)d_in[1];
    const float* sb      = (const float*)d_in[2];
    const float* gamma   = (const float*)d_in[3];
    const float* lnb     = (const float*)d_in[4];
    const float* qw      = (const float*)d_in[5];
    const float* qb      = (const float*)d_in[6];
    const float* kw      = (const float*)d_in[7];
    const float* kb      = (const float*)d_in[8];
    const float* vw      = (const float*)d_in[9];
    const float* vb      = (const float*)d_in[10];
    float* out = (float*)d_out;
    const int maskN = in_sizes[1];

    static int attr_done = 0;
    if (!attr_done) {
        cudaFuncSetAttribute(gemm_qkv_mma, cudaFuncAttributeMaxDynamicSharedMemorySize, GEMM_SMEM);
        cudaFuncSetAttribute(attn_mma_kernel, cudaFuncAttributeMaxDynamicSharedMemorySize, ATT_SMEM);
        attr_done = 1;
    }

    __nv_bfloat16 *xh = nullptr, *wh = nullptr;
    cudaGetSymbolAddress((void**)&xh, g_Xh);
    cudaGetSymbolAddress((void**)&wh, g_Wh);

    const int nX4 = BB * SS * DD / 4;
    const int nW4 = DD * DD / 4;
    tobf16_kernel<<<(nX4 + 255) / 256, 256>>>(x, xh, nX4);
    tobf16_kernel<<<(nW4 + 255) / 256, 256>>>(qw, wh, nW4);
    tobf16_kernel<<<(nW4 + 255) / 256, 256>>>(kw, wh + (size_t)DD * DD, nW4);
    tobf16_kernel<<<(nW4 + 255) / 256, 256>>>(vw, wh + (size_t)2 * DD * DD, nW4);

    zero_scratch_kernel<<<(BB * DD * 5 + 255) / 256, 256>>>();
    fourier_stats_kernel<<<dim3(16, BB), 256>>>(x);
    mask_scan_kernel<<<512, 256>>>(mask, maskN);
    dsp_ln_kernel<<<BB * SS, 256>>>(x, sb, gamma, lnb, out);
    gemm_qkv_mma<<<dim3(DD / BN, BB * SS / BM, 3), 256, GEMM_SMEM>>>(qb, kb, vb);
    attn_mma_kernel<<<dim3(SS / 128, BB * HH), 256, ATT_SMEM>>>(mask, out);
}